// round 7
// baseline (speedup 1.0000x reference)
#include <cuda_runtime.h>
#include <cuda_bf16.h>
#include <math.h>
#include <cstdint>

// ---------------------------------------------------------------------------
// SimpleGPT forward. R7: k_ffn rebuilt (smem-resident weights, no spills,
// grid 200, 2 blocks/SM); logits mma tile 128x256 (512 threads).
// B=64 T=50 V=32000 E=64 DH=128 H=8 M=256
// ---------------------------------------------------------------------------
constexpr int B   = 64;
constexpr int T   = 50;
constexpr int NV  = 32000;
constexpr int E   = 64;
constexpr int DH  = 128;
constexpr int H   = 8;
constexpr int FM  = 256;
constexpr int BT  = B * T;   // 3200
constexpr int OD  = H * DH;  // 1024

typedef unsigned long long u64;

__device__ __forceinline__ u64 ffma2(u64 a, u64 b, u64 c) {
    u64 d;
    asm("fma.rn.f32x2 %0, %1, %2, %3;" : "=l"(d) : "l"(a), "l"(b), "l"(c));
    return d;
}
__device__ __forceinline__ u64 bcast2(float x) {
    u64 d;
    unsigned xi = __float_as_uint(x);
    asm("mov.b64 %0, {%1, %1};" : "=l"(d) : "r"(xi));
    return d;
}
__device__ __forceinline__ u64 pack2f(float x, float y) {
    u64 d;
    unsigned xi = __float_as_uint(x), yi = __float_as_uint(y);
    asm("mov.b64 %0, {%1, %2};" : "=l"(d) : "r"(xi), "r"(yi));
    return d;
}
__device__ __forceinline__ u64 pk(uint32_t lo, uint32_t hi) {
    u64 d;
    asm("mov.b64 %0, {%1, %2};" : "=l"(d) : "r"(lo), "r"(hi));
    return d;
}
__device__ __forceinline__ float2 unpack2(u64 v) {
    unsigned lo, hi;
    asm("mov.b64 {%0, %1}, %2;" : "=r"(lo), "=r"(hi) : "l"(v));
    return make_float2(__uint_as_float(lo), __uint_as_float(hi));
}
__device__ __forceinline__ uint32_t smem_u32(const void* p) {
    uint32_t a;
    asm("{ .reg .u64 t; cvta.to.shared.u64 t, %1; cvt.u32.u64 %0, t; }" : "=r"(a) : "l"(p));
    return a;
}
#define SW128(x) ((x) ^ (((x) >> 3) & 0x70))

// Scratch
__device__ __align__(16) float g_q[B * H * T * DH];
__device__ __align__(16) float g_k[B * H * T * DH];
__device__ __align__(16) float g_v[B * H * T * DH];
__device__ __align__(16) float g_o[BT * OD];
__device__ __align__(16) __nv_bfloat16 g_yh[BT * E];
__device__ __align__(16) __nv_bfloat16 g_yl[BT * E];
__device__ __align__(16) __nv_bfloat16 g_wh[(size_t)NV * E];  // [n][k]
__device__ __align__(16) __nv_bfloat16 g_wl[(size_t)NV * E];  // [n][k]

// ---------------------------------------------------------------------------
// 0) Wf -> transposed bf16 hi/lo
// ---------------------------------------------------------------------------
__global__ void k_cvt_wf(const float* __restrict__ Wf) {
    __shared__ float s[64 * 65];
    int tid = threadIdx.x;
    int nb = blockIdx.x * 64;
#pragma unroll
    for (int it = 0; it < 16; it++) {
        int i = tid + it * 256;
        int k = i >> 6, j = i & 63;
        s[k * 65 + j] = Wf[(size_t)k * NV + nb + j];
    }
    __syncthreads();
#pragma unroll
    for (int it = 0; it < 8; it++) {
        int i = tid + it * 256;
        int n = i >> 5, k2 = (i & 31) * 2;
        float v0 = s[k2 * 65 + n];
        float v1 = s[(k2 + 1) * 65 + n];
        __nv_bfloat16 h0 = __float2bfloat16_rn(v0);
        __nv_bfloat16 h1 = __float2bfloat16_rn(v1);
        __nv_bfloat162 hh; hh.x = h0; hh.y = h1;
        __nv_bfloat162 ll;
        ll.x = __float2bfloat16_rn(v0 - __bfloat162float(h0));
        ll.y = __float2bfloat16_rn(v1 - __bfloat162float(h1));
        size_t o = (size_t)(nb + n) * 64 + k2;
        *(__nv_bfloat162*)(g_wh + o) = hh;
        *(__nv_bfloat162*)(g_wl + o) = ll;
    }
}

// ---------------------------------------------------------------------------
// 1) QKV (+ fused embedding). grid (B,H,3), 128 threads.
// ---------------------------------------------------------------------------
__global__ void k_qkv(const int* __restrict__ x,
                      const float* __restrict__ te, const float* __restrict__ pe,
                      const float* __restrict__ Wq, const float* __restrict__ bq,
                      const float* __restrict__ Wk, const float* __restrict__ bk,
                      const float* __restrict__ Wv, const float* __restrict__ bv) {
    __shared__ __align__(16) float h_s[T * E];
    int b = blockIdx.x, h = blockIdx.y, m = blockIdx.z;
    int d = threadIdx.x;

    for (int i = d; i < T * E; i += 128) {
        int t = i >> 6;
        h_s[i] = te[x[b * T + t] * E + (i & 63)] + pe[i];
    }

    const float* W    = (m == 0) ? Wq : ((m == 1) ? Wk : Wv);
    const float* bias = (m == 0) ? bq : ((m == 1) ? bk : bv);
    float* out = ((m == 0) ? g_q : ((m == 1) ? g_k : g_v)) + ((size_t)(b * H + h) * T) * DH;

    u64 wp[32];
#pragma unroll
    for (int e2 = 0; e2 < 32; e2++)
        wp[e2] = pack2f(W[(h * E + 2 * e2) * DH + d], W[(h * E + 2 * e2 + 1) * DH + d]);
    float bb = bias[h * DH + d];
    __syncthreads();

    for (int t = 0; t < T; t++) {
        u64 a0 = 0ull, a1 = 0ull;
        const u64* hp = (const u64*)(h_s + t * E);
#pragma unroll
        for (int e2 = 0; e2 < 32; e2 += 2) {
            a0 = ffma2(wp[e2],     hp[e2],     a0);
            a1 = ffma2(wp[e2 + 1], hp[e2 + 1], a1);
        }
        float2 s0 = unpack2(a0), s1 = unpack2(a1);
        out[t * DH + d] = s0.x + s0.y + s1.x + s1.y + bb;
    }
}

// ---------------------------------------------------------------------------
// 2) Attention (unchanged from R6 — validated win)
// ---------------------------------------------------------------------------
constexpr int KP132 = 132;
constexpr int A_KOFF = T * KP132;
constexpr int A_VOFF = A_KOFF + T * DH;
constexpr int A_QOFF = A_VOFF;
constexpr int A_POFF = A_QOFF + 8 * 8 * DH;
constexpr int A_TOTF = A_POFF + 8 * 8 * 64;

__global__ void __launch_bounds__(256)
k_attn() {
    extern __shared__ float sm[];
    float* K_s = sm;
    float* V_s = sm + A_KOFF;
    float* q_s = sm + A_QOFF;
    float* p_s = sm + A_POFF;

    int b = blockIdx.x, h = blockIdx.y;
    int tid = threadIdx.x, w = tid >> 5, lane = tid & 31;
    size_t base = ((size_t)(b * H + h) * T) * DH;

    for (int i = tid; i < T * 32; i += 256) {
        int s = i >> 5, c4 = (i & 31) * 4;
        *(float4*)(K_s + s * KP132 + c4) = *(const float4*)(g_k + base + s * DH + c4);
        *(float4*)(V_s + s * DH + c4)    = *(const float4*)(g_v + base + s * DH + c4);
    }
    __syncthreads();

#pragma unroll
    for (int j = 0; j < 7; j++) {
        int t = w + 8 * j;
        if (t < T)
            *(float4*)(q_s + (w * 8 + j) * DH + lane * 4) =
                *(const float4*)(g_q + base + (size_t)t * DH + lane * 4);
    }
    __syncwarp();

    int s0 = lane, s1 = lane + 32;
    const float* k0p = K_s + s0 * KP132;
    const float* k1p = K_s + s1 * KP132;

    u64 acc[7][2];
#pragma unroll
    for (int j = 0; j < 7; j++) { acc[j][0] = 0ull; acc[j][1] = 0ull; }

#pragma unroll 8
    for (int c = 0; c < DH; c += 4) {
        uint4 k0 = *(const uint4*)(k0p + c);
        uint4 k1 = *(const uint4*)(k1p + c);
        u64 k0a = pk(k0.x, k0.y), k0b = pk(k0.z, k0.w);
        u64 k1a = pk(k1.x, k1.y), k1b = pk(k1.z, k1.w);
#pragma unroll
        for (int j = 0; j < 7; j++) {
            uint4 qv = *(const uint4*)(q_s + (w * 8 + j) * DH + c);
            u64 qa = pk(qv.x, qv.y), qb = pk(qv.z, qv.w);
            acc[j][0] = ffma2(qb, k0b, ffma2(qa, k0a, acc[j][0]));
            acc[j][1] = ffma2(qb, k1b, ffma2(qa, k1a, acc[j][1]));
        }
    }

    const float scale = 0.0883883476483184f;
    float sum[7], inv[7];
#pragma unroll
    for (int j = 0; j < 7; j++) {
        int t = w + 8 * j;
        bool valid = t < T;
        float2 f0 = unpack2(acc[j][0]);
        float2 f1 = unpack2(acc[j][1]);
        float sc0 = (f0.x + f0.y) * scale;
        float sc1 = (f1.x + f1.y) * scale;
        float e0 = (valid && s0 <= t) ? __expf(sc0) : 0.f;
        float e1 = (valid && s1 <= t) ? __expf(sc1) : 0.f;
        p_s[(w * 8 + j) * 64 + s0] = e0;
        p_s[(w * 8 + j) * 64 + s1] = e1;
        sum[j] = e0 + e1;
    }
#pragma unroll
    for (int off = 16; off; off >>= 1) {
#pragma unroll
        for (int j = 0; j < 7; j++)
            sum[j] += __shfl_xor_sync(0xffffffffu, sum[j], off);
    }
#pragma unroll
    for (int j = 0; j < 7; j++) inv[j] = 1.0f / sum[j];
    __syncwarp();

    u64 av[7][2];
#pragma unroll
    for (int j = 0; j < 7; j++) { av[j][0] = 0ull; av[j][1] = 0ull; }

    const float* vb = V_s + lane * 4;
    const float* pb = p_s + w * 8 * 64;
#pragma unroll 2
    for (int s = 0; s < T; s++) {
        uint4 vv = *(const uint4*)(vb + s * DH);
        u64 v01 = pk(vv.x, vv.y), v23 = pk(vv.z, vv.w);
#pragma unroll
        for (int j = 0; j < 7; j++) {
            u64 pj = bcast2(pb[j * 64 + s]);
            av[j][0] = ffma2(pj, v01, av[j][0]);
            av[j][1] = ffma2(pj, v23, av[j][1]);
        }
    }

#pragma unroll
    for (int j = 0; j < 7; j++) {
        int t = w + 8 * j;
        if (t < T) {
            float2 o01 = unpack2(av[j][0]), o23 = unpack2(av[j][1]);
            float4 ov = make_float4(o01.x * inv[j], o01.y * inv[j],
                                    o23.x * inv[j], o23.y * inv[j]);
            *(float4*)(g_o + (size_t)(b * T + t) * OD + h * DH + lane * 4) = ov;
        }
    }
}

// ---------------------------------------------------------------------------
// 3) Fused FFN v3: 16 rows/block (grid 200), 256 threads, 88KB smem
//    (2 blocks/SM). All weights smem-resident; NO per-thread weight arrays.
//    Region R1 (16384 floats) reused: Wo-tiles -> W1 -> W2.
// ---------------------------------------------------------------------------
constexpr int FR1   = 0;          // 16384 floats (64KB), phase-dependent
constexpr int F_AS  = 16384;      // a: 16x64
constexpr int F_MT  = 17408;      // m^T: 256x18
constexpr int F_TOTF = 22016;     // 88064 B

__device__ __forceinline__ float gelu_exact(float x) {
    return 0.5f * x * (1.0f + erff(x * 0.70710678118654752f));
}

__global__ void __launch_bounds__(256)
k_ffn(const float* __restrict__ Wo, const float* __restrict__ bo,
      const float* __restrict__ W1, const float* __restrict__ b1,
      const float* __restrict__ W2, const float* __restrict__ b2) {
    extern __shared__ float sm[];
    float* R1   = sm + FR1;
    float* a_s  = sm + F_AS;
    float* m_sT = sm + F_MT;

    int tid = threadIdx.x;
    int rb  = blockIdx.x * 16;
    int e   = tid & 63;
    int rg  = tid >> 6;            // 0..3 -> rows rg*4..+3

    // ---- Phase 1: a = o @ Wo + bo  (Wo_s = R1[0:8192], o_sT = R1[8192:+2560])
    float* Wo_s = R1;
    float* o_sT = R1 + 8192;       // 128 x 20 (16 rows, pitch 20)
    u64 acc0 = 0ull, acc1 = 0ull;
    for (int kt = 0; kt < OD; kt += 128) {
        for (int i = tid; i < 8192; i += 256) Wo_s[i] = Wo[kt * 64 + i];
        for (int i = tid; i < 2048; i += 256) {
            int k = i & 127, r = i >> 7;
            o_sT[k * 20 + r] = g_o[(size_t)(rb + r) * OD + kt + k];
        }
        __syncthreads();
#pragma unroll 4
        for (int k = 0; k < 128; k++) {
            u64 wv = bcast2(Wo_s[k * 64 + e]);
            const u64* op = (const u64*)(o_sT + k * 20 + rg * 4);
            acc0 = ffma2(wv, op[0], acc0);
            acc1 = ffma2(wv, op[1], acc1);
        }
        __syncthreads();
    }
    {
        float bov = bo[e];
        float2 c01 = unpack2(acc0), c23 = unpack2(acc1);
        a_s[(rg * 4 + 0) * 64 + e] = c01.x + bov;
        a_s[(rg * 4 + 1) * 64 + e] = c01.y + bov;
        a_s[(rg * 4 + 2) * 64 + e] = c23.x + bov;
        a_s[(rg * 4 + 3) * 64 + e] = c23.y + bov;
    }
    __syncthreads();

    // ---- Phase 2: m^T = gelu(a @ W1 + b1). W1 staged verbatim into R1:
    //      row-major [64][256] -> u64 view [64][128] of j-pairs.
    for (int i = tid; i < 16384; i += 256) R1[i] = W1[i];
    __syncthreads();
    {
        int j2 = tid & 127;        // column pair (2*j2, 2*j2+1)
        int rh = tid >> 7;         // 0..1 -> rows rh*8..+7
        const u64* W1u = (const u64*)R1;
        u64 macc[8];
#pragma unroll
        for (int i = 0; i < 8; i++) macc[i] = 0ull;
#pragma unroll 4
        for (int ee = 0; ee < 64; ee++) {
            u64 wv = W1u[ee * 128 + j2];
#pragma unroll
            for (int i = 0; i < 8; i++)
                macc[i] = ffma2(bcast2(a_s[(rh * 8 + i) * 64 + ee]), wv, macc[i]);
        }
        float bj0 = b1[2 * j2], bj1 = b1[2 * j2 + 1];
#pragma unroll
        for (int i = 0; i < 8; i++) {
            int r = rh * 8 + i;
            float2 v = unpack2(macc[i]);
            m_sT[(2 * j2) * 18 + r]     = gelu_exact(v.x + bj0);
            m_sT[(2 * j2 + 1) * 18 + r] = gelu_exact(v.y + bj1);
        }
    }
    __syncthreads();

    // ---- Phase 3: y = m @ W2 + b2 -> bf16 hi/lo. W2 staged verbatim.
    for (int i = tid; i < 16384; i += 256) R1[i] = W2[i];
    __syncthreads();
    {
        u64 c0 = 0ull, c1 = 0ull;
#pragma unroll 4
        for (int j = 0; j < FM; j++) {
            u64 wv = bcast2(R1[j * 64 + e]);
            const u64* mp = (const u64*)(m_sT + j * 18 + rg * 4);
            c0 = ffma2(wv, mp[0], c0);
            c1 = ffma2(wv, mp[1], c1);
        }
        float b2v = b2[e];
        float2 d01 = unpack2(c0), d23 = unpack2(c1);
        float yv[4] = {d01.x + b2v, d01.y + b2v, d23.x + b2v, d23.y + b2v};
#pragma unroll
        for (int i = 0; i < 4; i++) {
            int r = rb + rg * 4 + i;
            __nv_bfloat16 hi = __float2bfloat16_rn(yv[i]);
            g_yh[r * 64 + e] = hi;
            g_yl[r * 64 + e] = __float2bfloat16_rn(yv[i] - __bfloat162float(hi));
        }
    }
}

// ---------------------------------------------------------------------------
// 4) Logits GEMM via mma.sync bf16. CTA tile 128x256, K=64, 512 threads
//    (16 warps = 4m x 4n). D = yh@Wh + yh@Wl + yl@Wh.
// ---------------------------------------------------------------------------
constexpr int S_AH   = 0;
constexpr int S_AL   = 16384;
constexpr int S_BH   = 32768;     // 256 rows x 128B = 32KB
constexpr int S_BL   = 65536;
constexpr int S_BIAS = 98304;     // 256 floats
constexpr int S_TOT  = 99328;

__device__ __forceinline__ void ldm4(uint32_t& r0, uint32_t& r1,
                                     uint32_t& r2, uint32_t& r3, uint32_t addr) {
    asm volatile("ldmatrix.sync.aligned.m8n8.x4.shared.b16 {%0,%1,%2,%3}, [%4];"
                 : "=r"(r0), "=r"(r1), "=r"(r2), "=r"(r3) : "r"(addr));
}
__device__ __forceinline__ void mma16816(float* c, uint32_t a0, uint32_t a1,
                                         uint32_t a2, uint32_t a3,
                                         uint32_t b0, uint32_t b1) {
    asm volatile(
        "mma.sync.aligned.m16n8k16.row.col.f32.bf16.bf16.f32 "
        "{%0,%1,%2,%3}, {%4,%5,%6,%7}, {%8,%9}, {%0,%1,%2,%3};"
        : "+f"(c[0]), "+f"(c[1]), "+f"(c[2]), "+f"(c[3])
        : "r"(a0), "r"(a1), "r"(a2), "r"(a3), "r"(b0), "r"(b1));
}

__global__ void __launch_bounds__(512)
k_logits_mma(const float* __restrict__ bf, float* __restrict__ out) {
    extern __shared__ char smem[];
    uint32_t sb = smem_u32(smem);
    int tid = threadIdx.x, wid = tid >> 5, lane = tid & 31;
    int nb = blockIdx.x * 256;
    int rb = blockIdx.y * 128;
    int wm = wid & 3;        // rows wm*32..+31
    int wn = wid >> 2;       // cols wn*64..+63 (0..3)

    if (tid < 256) *(float*)(smem + S_BIAS + tid * 4) = bf[nb + tid];

    for (int idx = tid; idx < 1024; idx += 512) {
        int r = idx >> 3, c = idx & 7;
        uint32_t sw = SW128((uint32_t)(r * 128 + c * 16));
        size_t ga = (size_t)(rb + r) * 64 + c * 8;
        *(uint4*)(smem + S_AH + sw) = *(const uint4*)(g_yh + ga);
        *(uint4*)(smem + S_AL + sw) = *(const uint4*)(g_yl + ga);
    }
    for (int idx = tid; idx < 2048; idx += 512) {
        int r = idx >> 3, c = idx & 7;
        uint32_t sw = SW128((uint32_t)(r * 128 + c * 16));
        size_t gb = (size_t)(nb + r) * 64 + c * 8;
        *(uint4*)(smem + S_BH + sw) = *(const uint4*)(g_wh + gb);
        *(uint4*)(smem + S_BL + sw) = *(const uint4*)(g_wl + gb);
    }
    __syncthreads();

    float c[2][8][4];
#pragma unroll
    for (int mb = 0; mb < 2; mb++)
#pragma unroll
        for (int nbk = 0; nbk < 8; nbk++)
#pragma unroll
            for (int j = 0; j < 4; j++) c[mb][nbk][j] = 0.f;

    int a_row  = wm * 32 + (lane & 15);
    int a_colb = (lane >> 4) * 16;
    int b_n    = wn * 64 + ((lane >> 3) >> 1) * 8 + (lane & 7);
    int b_kb   = ((lane >> 3) & 1) * 16;

#pragma unroll
    for (int p = 0; p < 3; p++) {
        uint32_t abase = sb + ((p < 2) ? S_AH : S_AL);
        uint32_t bbase = sb + ((p == 1) ? S_BL : S_BH);
#pragma unroll
        for (int ks = 0; ks < 4; ks++) {
            uint32_t a0[4], a1[4];
            ldm4(a0[0], a0[1], a0[2], a0[3],
                 abase + SW128((uint32_t)(a_row * 128 + a_colb + ks * 32)));
            ldm4(a1[0], a1[1], a1[2], a1[3],
                 abase + SW128((uint32_t)((a_row + 16) * 128 + a_colb + ks * 32)));
#pragma unroll
            for (int q = 0; q < 4; q++) {
                uint32_t b0, b1, b2, b3;
                ldm4(b0, b1, b2, b3,
                     bbase + SW128((uint32_t)((b_n + q * 16) * 128 + b_kb + ks * 32)));
                mma16816(c[0][2 * q],     a0[0], a0[1], a0[2], a0[3], b0, b1);
                mma16816(c[0][2 * q + 1], a0[0], a0[1], a0[2], a0[3], b2, b3);
                mma16816(c[1][2 * q],     a1[0], a1[1], a1[2], a1[3], b0, b1);
                mma16816(c[1][2 * q + 1], a1[0], a1[1], a1[2], a1[3], b2, b3);
            }
        }
    }

    const float* bias_s = (const float*)(smem + S_BIAS);
    int g = lane >> 2, q4 = lane & 3;
#pragma unroll
    for (int mb = 0; mb < 2; mb++) {
        int row = rb + wm * 32 + mb * 16 + g;
        float* orow = out + (size_t)row * NV;
#pragma unroll
        for (int nbk = 0; nbk < 8; nbk++) {
            int coff = wn * 64 + nbk * 8 + 2 * q4;
            int col = nb + coff;
            float bx = bias_s[coff], by = bias_s[coff + 1];
            float2 v0 = make_float2(c[mb][nbk][0] + bx, c[mb][nbk][1] + by);
            float2 v1 = make_float2(c[mb][nbk][2] + bx, c[mb][nbk][3] + by);
            *(float2*)(orow + col)          = v0;
            *(float2*)(orow + 8 * NV + col) = v1;
        }
    }
}

// ---------------------------------------------------------------------------
extern "C" void kernel_launch(void* const* d_in, const int* in_sizes, int n_in,
                              void* d_out, int out_size) {
    (void)in_sizes; (void)n_in; (void)out_size;
    const int*   x  = (const int*)d_in[0];
    const float* te = (const float*)d_in[1];
    const float* pe = (const float*)d_in[2];
    const float* Wq = (const float*)d_in[3];  const float* bq = (const float*)d_in[4];
    const float* Wk = (const float*)d_in[5];  const float* bk = (const float*)d_in[6];
    const float* Wv = (const float*)d_in[7];  const float* bv = (const float*)d_in[8];
    const float* Wo = (const float*)d_in[9];  const float* bo = (const float*)d_in[10];
    const float* W1 = (const float*)d_in[11]; const float* b1 = (const float*)d_in[12];
    const float* W2 = (const float*)d_in[13]; const float* b2 = (const float*)d_in[14];
    const float* Wf = (const float*)d_in[15]; const float* bf = (const float*)d_in[16];
    float* out = (float*)d_out;

    k_cvt_wf<<<NV / 64, 256>>>(Wf);
    k_qkv<<<dim3(B, H, 3), 128>>>(x, te, pe, Wq, bq, Wk, bk, Wv, bv);

    int attn_smem = A_TOTF * (int)sizeof(float);
    cudaFuncSetAttribute(k_attn, cudaFuncAttributeMaxDynamicSharedMemorySize, attn_smem);
    k_attn<<<dim3(B, H), 256, attn_smem>>>();

    int ffn_smem = F_TOTF * (int)sizeof(float);    // 88KB
    cudaFuncSetAttribute(k_ffn, cudaFuncAttributeMaxDynamicSharedMemorySize, ffn_smem);
    k_ffn<<<BT / 16, 256, ffn_smem>>>(Wo, bo, W1, b1, W2, b2);

    cudaFuncSetAttribute(k_logits_mma, cudaFuncAttributeMaxDynamicSharedMemorySize, S_TOT);
    k_logits_mma<<<dim3(NV / 256, BT / 128), 512, S_TOT>>>(bf, out);
}

// round 8
// speedup vs baseline: 1.2144x; 1.2144x over previous
#include <cuda_runtime.h>
#include <cuda_bf16.h>
#include <math.h>
#include <cstdint>

// ---------------------------------------------------------------------------
// SimpleGPT forward. R8: persistent column-stripe logits GEMM (B resident,
// cp.async double-buffered A, bias in regs). ffn/attn/qkv from R7.
// B=64 T=50 V=32000 E=64 DH=128 H=8 M=256
// ---------------------------------------------------------------------------
constexpr int B   = 64;
constexpr int T   = 50;
constexpr int NV  = 32000;
constexpr int E   = 64;
constexpr int DH  = 128;
constexpr int H   = 8;
constexpr int FM  = 256;
constexpr int BT  = B * T;   // 3200
constexpr int OD  = H * DH;  // 1024

typedef unsigned long long u64;

__device__ __forceinline__ u64 ffma2(u64 a, u64 b, u64 c) {
    u64 d;
    asm("fma.rn.f32x2 %0, %1, %2, %3;" : "=l"(d) : "l"(a), "l"(b), "l"(c));
    return d;
}
__device__ __forceinline__ u64 bcast2(float x) {
    u64 d;
    unsigned xi = __float_as_uint(x);
    asm("mov.b64 %0, {%1, %1};" : "=l"(d) : "r"(xi));
    return d;
}
__device__ __forceinline__ u64 pack2f(float x, float y) {
    u64 d;
    unsigned xi = __float_as_uint(x), yi = __float_as_uint(y);
    asm("mov.b64 %0, {%1, %2};" : "=l"(d) : "r"(xi), "r"(yi));
    return d;
}
__device__ __forceinline__ u64 pk(uint32_t lo, uint32_t hi) {
    u64 d;
    asm("mov.b64 %0, {%1, %2};" : "=l"(d) : "r"(lo), "r"(hi));
    return d;
}
__device__ __forceinline__ float2 unpack2(u64 v) {
    unsigned lo, hi;
    asm("mov.b64 {%0, %1}, %2;" : "=r"(lo), "=r"(hi) : "l"(v));
    return make_float2(__uint_as_float(lo), __uint_as_float(hi));
}
__device__ __forceinline__ uint32_t smem_u32(const void* p) {
    uint32_t a;
    asm("{ .reg .u64 t; cvta.to.shared.u64 t, %1; cvt.u32.u64 %0, t; }" : "=r"(a) : "l"(p));
    return a;
}
__device__ __forceinline__ void cpa16(uint32_t saddr, const void* gptr) {
    asm volatile("cp.async.cg.shared.global [%0], [%1], 16;"
                 :: "r"(saddr), "l"(__cvta_generic_to_global(gptr)) : "memory");
}
#define CPA_COMMIT() asm volatile("cp.async.commit_group;" ::: "memory")
#define CPA_WAIT1()  asm volatile("cp.async.wait_group 1;" ::: "memory")
#define SW128(x) ((x) ^ (((x) >> 3) & 0x70))

// Scratch
__device__ __align__(16) float g_q[B * H * T * DH];
__device__ __align__(16) float g_k[B * H * T * DH];
__device__ __align__(16) float g_v[B * H * T * DH];
__device__ __align__(16) float g_o[BT * OD];
__device__ __align__(16) __nv_bfloat16 g_yh[BT * E];
__device__ __align__(16) __nv_bfloat16 g_yl[BT * E];
__device__ __align__(16) __nv_bfloat16 g_wh[(size_t)NV * E];  // [n][k]
__device__ __align__(16) __nv_bfloat16 g_wl[(size_t)NV * E];  // [n][k]

// ---------------------------------------------------------------------------
// 0) Wf -> transposed bf16 hi/lo
// ---------------------------------------------------------------------------
__global__ void k_cvt_wf(const float* __restrict__ Wf) {
    __shared__ float s[64 * 65];
    int tid = threadIdx.x;
    int nb = blockIdx.x * 64;
#pragma unroll
    for (int it = 0; it < 16; it++) {
        int i = tid + it * 256;
        int k = i >> 6, j = i & 63;
        s[k * 65 + j] = Wf[(size_t)k * NV + nb + j];
    }
    __syncthreads();
#pragma unroll
    for (int it = 0; it < 8; it++) {
        int i = tid + it * 256;
        int n = i >> 5, k2 = (i & 31) * 2;
        float v0 = s[k2 * 65 + n];
        float v1 = s[(k2 + 1) * 65 + n];
        __nv_bfloat16 h0 = __float2bfloat16_rn(v0);
        __nv_bfloat16 h1 = __float2bfloat16_rn(v1);
        __nv_bfloat162 hh; hh.x = h0; hh.y = h1;
        __nv_bfloat162 ll;
        ll.x = __float2bfloat16_rn(v0 - __bfloat162float(h0));
        ll.y = __float2bfloat16_rn(v1 - __bfloat162float(h1));
        size_t o = (size_t)(nb + n) * 64 + k2;
        *(__nv_bfloat162*)(g_wh + o) = hh;
        *(__nv_bfloat162*)(g_wl + o) = ll;
    }
}

// ---------------------------------------------------------------------------
// 1) QKV (+ fused embedding)
// ---------------------------------------------------------------------------
__global__ void k_qkv(const int* __restrict__ x,
                      const float* __restrict__ te, const float* __restrict__ pe,
                      const float* __restrict__ Wq, const float* __restrict__ bq,
                      const float* __restrict__ Wk, const float* __restrict__ bk,
                      const float* __restrict__ Wv, const float* __restrict__ bv) {
    __shared__ __align__(16) float h_s[T * E];
    int b = blockIdx.x, h = blockIdx.y, m = blockIdx.z;
    int d = threadIdx.x;

    for (int i = d; i < T * E; i += 128) {
        int t = i >> 6;
        h_s[i] = te[x[b * T + t] * E + (i & 63)] + pe[i];
    }

    const float* W    = (m == 0) ? Wq : ((m == 1) ? Wk : Wv);
    const float* bias = (m == 0) ? bq : ((m == 1) ? bk : bv);
    float* out = ((m == 0) ? g_q : ((m == 1) ? g_k : g_v)) + ((size_t)(b * H + h) * T) * DH;

    u64 wp[32];
#pragma unroll
    for (int e2 = 0; e2 < 32; e2++)
        wp[e2] = pack2f(W[(h * E + 2 * e2) * DH + d], W[(h * E + 2 * e2 + 1) * DH + d]);
    float bb = bias[h * DH + d];
    __syncthreads();

    for (int t = 0; t < T; t++) {
        u64 a0 = 0ull, a1 = 0ull;
        const u64* hp = (const u64*)(h_s + t * E);
#pragma unroll
        for (int e2 = 0; e2 < 32; e2 += 2) {
            a0 = ffma2(wp[e2],     hp[e2],     a0);
            a1 = ffma2(wp[e2 + 1], hp[e2 + 1], a1);
        }
        float2 s0 = unpack2(a0), s1 = unpack2(a1);
        out[t * DH + d] = s0.x + s0.y + s1.x + s1.y + bb;
    }
}

// ---------------------------------------------------------------------------
// 2) Attention (R6 version, validated)
// ---------------------------------------------------------------------------
constexpr int KP132 = 132;
constexpr int A_KOFF = T * KP132;
constexpr int A_VOFF = A_KOFF + T * DH;
constexpr int A_QOFF = A_VOFF;
constexpr int A_POFF = A_QOFF + 8 * 8 * DH;
constexpr int A_TOTF = A_POFF + 8 * 8 * 64;

__global__ void __launch_bounds__(256)
k_attn() {
    extern __shared__ float sm[];
    float* K_s = sm;
    float* V_s = sm + A_KOFF;
    float* q_s = sm + A_QOFF;
    float* p_s = sm + A_POFF;

    int b = blockIdx.x, h = blockIdx.y;
    int tid = threadIdx.x, w = tid >> 5, lane = tid & 31;
    size_t base = ((size_t)(b * H + h) * T) * DH;

    for (int i = tid; i < T * 32; i += 256) {
        int s = i >> 5, c4 = (i & 31) * 4;
        *(float4*)(K_s + s * KP132 + c4) = *(const float4*)(g_k + base + s * DH + c4);
        *(float4*)(V_s + s * DH + c4)    = *(const float4*)(g_v + base + s * DH + c4);
    }
    __syncthreads();

#pragma unroll
    for (int j = 0; j < 7; j++) {
        int t = w + 8 * j;
        if (t < T)
            *(float4*)(q_s + (w * 8 + j) * DH + lane * 4) =
                *(const float4*)(g_q + base + (size_t)t * DH + lane * 4);
    }
    __syncwarp();

    int s0 = lane, s1 = lane + 32;
    const float* k0p = K_s + s0 * KP132;
    const float* k1p = K_s + s1 * KP132;

    u64 acc[7][2];
#pragma unroll
    for (int j = 0; j < 7; j++) { acc[j][0] = 0ull; acc[j][1] = 0ull; }

#pragma unroll 8
    for (int c = 0; c < DH; c += 4) {
        uint4 k0 = *(const uint4*)(k0p + c);
        uint4 k1 = *(const uint4*)(k1p + c);
        u64 k0a = pk(k0.x, k0.y), k0b = pk(k0.z, k0.w);
        u64 k1a = pk(k1.x, k1.y), k1b = pk(k1.z, k1.w);
#pragma unroll
        for (int j = 0; j < 7; j++) {
            uint4 qv = *(const uint4*)(q_s + (w * 8 + j) * DH + c);
            u64 qa = pk(qv.x, qv.y), qb = pk(qv.z, qv.w);
            acc[j][0] = ffma2(qb, k0b, ffma2(qa, k0a, acc[j][0]));
            acc[j][1] = ffma2(qb, k1b, ffma2(qa, k1a, acc[j][1]));
        }
    }

    const float scale = 0.0883883476483184f;
    float sum[7], inv[7];
#pragma unroll
    for (int j = 0; j < 7; j++) {
        int t = w + 8 * j;
        bool valid = t < T;
        float2 f0 = unpack2(acc[j][0]);
        float2 f1 = unpack2(acc[j][1]);
        float sc0 = (f0.x + f0.y) * scale;
        float sc1 = (f1.x + f1.y) * scale;
        float e0 = (valid && s0 <= t) ? __expf(sc0) : 0.f;
        float e1 = (valid && s1 <= t) ? __expf(sc1) : 0.f;
        p_s[(w * 8 + j) * 64 + s0] = e0;
        p_s[(w * 8 + j) * 64 + s1] = e1;
        sum[j] = e0 + e1;
    }
#pragma unroll
    for (int off = 16; off; off >>= 1) {
#pragma unroll
        for (int j = 0; j < 7; j++)
            sum[j] += __shfl_xor_sync(0xffffffffu, sum[j], off);
    }
#pragma unroll
    for (int j = 0; j < 7; j++) inv[j] = 1.0f / sum[j];
    __syncwarp();

    u64 av[7][2];
#pragma unroll
    for (int j = 0; j < 7; j++) { av[j][0] = 0ull; av[j][1] = 0ull; }

    const float* vb = V_s + lane * 4;
    const float* pb = p_s + w * 8 * 64;
#pragma unroll 2
    for (int s = 0; s < T; s++) {
        uint4 vv = *(const uint4*)(vb + s * DH);
        u64 v01 = pk(vv.x, vv.y), v23 = pk(vv.z, vv.w);
#pragma unroll
        for (int j = 0; j < 7; j++) {
            u64 pj = bcast2(pb[j * 64 + s]);
            av[j][0] = ffma2(pj, v01, av[j][0]);
            av[j][1] = ffma2(pj, v23, av[j][1]);
        }
    }

#pragma unroll
    for (int j = 0; j < 7; j++) {
        int t = w + 8 * j;
        if (t < T) {
            float2 o01 = unpack2(av[j][0]), o23 = unpack2(av[j][1]);
            float4 ov = make_float4(o01.x * inv[j], o01.y * inv[j],
                                    o23.x * inv[j], o23.y * inv[j]);
            *(float4*)(g_o + (size_t)(b * T + t) * OD + h * DH + lane * 4) = ov;
        }
    }
}

// ---------------------------------------------------------------------------
// 3) Fused FFN (R7 version, measured 80.6us, regs=48)
// ---------------------------------------------------------------------------
constexpr int FR1   = 0;
constexpr int F_AS  = 16384;
constexpr int F_MT  = 17408;
constexpr int F_TOTF = 22016;

__device__ __forceinline__ float gelu_exact(float x) {
    return 0.5f * x * (1.0f + erff(x * 0.70710678118654752f));
}

__global__ void __launch_bounds__(256)
k_ffn(const float* __restrict__ Wo, const float* __restrict__ bo,
      const float* __restrict__ W1, const float* __restrict__ b1,
      const float* __restrict__ W2, const float* __restrict__ b2) {
    extern __shared__ float sm[];
    float* R1   = sm + FR1;
    float* a_s  = sm + F_AS;
    float* m_sT = sm + F_MT;

    int tid = threadIdx.x;
    int rb  = blockIdx.x * 16;
    int e   = tid & 63;
    int rg  = tid >> 6;

    float* Wo_s = R1;
    float* o_sT = R1 + 8192;
    u64 acc0 = 0ull, acc1 = 0ull;
    for (int kt = 0; kt < OD; kt += 128) {
        for (int i = tid; i < 8192; i += 256) Wo_s[i] = Wo[kt * 64 + i];
        for (int i = tid; i < 2048; i += 256) {
            int k = i & 127, r = i >> 7;
            o_sT[k * 20 + r] = g_o[(size_t)(rb + r) * OD + kt + k];
        }
        __syncthreads();
#pragma unroll 4
        for (int k = 0; k < 128; k++) {
            u64 wv = bcast2(Wo_s[k * 64 + e]);
            const u64* op = (const u64*)(o_sT + k * 20 + rg * 4);
            acc0 = ffma2(wv, op[0], acc0);
            acc1 = ffma2(wv, op[1], acc1);
        }
        __syncthreads();
    }
    {
        float bov = bo[e];
        float2 c01 = unpack2(acc0), c23 = unpack2(acc1);
        a_s[(rg * 4 + 0) * 64 + e] = c01.x + bov;
        a_s[(rg * 4 + 1) * 64 + e] = c01.y + bov;
        a_s[(rg * 4 + 2) * 64 + e] = c23.x + bov;
        a_s[(rg * 4 + 3) * 64 + e] = c23.y + bov;
    }
    __syncthreads();

    for (int i = tid; i < 16384; i += 256) R1[i] = W1[i];
    __syncthreads();
    {
        int j2 = tid & 127;
        int rh = tid >> 7;
        const u64* W1u = (const u64*)R1;
        u64 macc[8];
#pragma unroll
        for (int i = 0; i < 8; i++) macc[i] = 0ull;
#pragma unroll 4
        for (int ee = 0; ee < 64; ee++) {
            u64 wv = W1u[ee * 128 + j2];
#pragma unroll
            for (int i = 0; i < 8; i++)
                macc[i] = ffma2(bcast2(a_s[(rh * 8 + i) * 64 + ee]), wv, macc[i]);
        }
        float bj0 = b1[2 * j2], bj1 = b1[2 * j2 + 1];
#pragma unroll
        for (int i = 0; i < 8; i++) {
            int r = rh * 8 + i;
            float2 v = unpack2(macc[i]);
            m_sT[(2 * j2) * 18 + r]     = gelu_exact(v.x + bj0);
            m_sT[(2 * j2 + 1) * 18 + r] = gelu_exact(v.y + bj1);
        }
    }
    __syncthreads();

    for (int i = tid; i < 16384; i += 256) R1[i] = W2[i];
    __syncthreads();
    {
        u64 c0 = 0ull, c1 = 0ull;
#pragma unroll 4
        for (int j = 0; j < FM; j++) {
            u64 wv = bcast2(R1[j * 64 + e]);
            const u64* mp = (const u64*)(m_sT + j * 18 + rg * 4);
            c0 = ffma2(wv, mp[0], c0);
            c1 = ffma2(wv, mp[1], c1);
        }
        float b2v = b2[e];
        float2 d01 = unpack2(c0), d23 = unpack2(c1);
        float yv[4] = {d01.x + b2v, d01.y + b2v, d23.x + b2v, d23.y + b2v};
#pragma unroll
        for (int i = 0; i < 4; i++) {
            int r = rb + rg * 4 + i;
            __nv_bfloat16 hi = __float2bfloat16_rn(yv[i]);
            g_yh[r * 64 + e] = hi;
            g_yl[r * 64 + e] = __float2bfloat16_rn(yv[i] - __bfloat162float(hi));
        }
    }
}

// ---------------------------------------------------------------------------
// 4) Logits GEMM, persistent column-stripe. 250 blocks x 128 cols; each
//    loops 50 row-tiles of 64. B (Wh/Wl, 32KB) resident; A (yh/yl, 16KB)
//    cp.async double-buffered. 256 threads = 8 warps (2m x 4n).
// ---------------------------------------------------------------------------
constexpr int S_BH = 0;          // 128 n-rows x 128B
constexpr int S_BL = 16384;
constexpr int S_A  = 32768;      // two buffers of 16KB (yh 8KB + yl 8KB)
constexpr int S_TOT = 65536;

__device__ __forceinline__ void ldm4(uint32_t& r0, uint32_t& r1,
                                     uint32_t& r2, uint32_t& r3, uint32_t addr) {
    asm volatile("ldmatrix.sync.aligned.m8n8.x4.shared.b16 {%0,%1,%2,%3}, [%4];"
                 : "=r"(r0), "=r"(r1), "=r"(r2), "=r"(r3) : "r"(addr));
}
__device__ __forceinline__ void mma16816(float* c, uint32_t a0, uint32_t a1,
                                         uint32_t a2, uint32_t a3,
                                         uint32_t b0, uint32_t b1) {
    asm volatile(
        "mma.sync.aligned.m16n8k16.row.col.f32.bf16.bf16.f32 "
        "{%0,%1,%2,%3}, {%4,%5,%6,%7}, {%8,%9}, {%0,%1,%2,%3};"
        : "+f"(c[0]), "+f"(c[1]), "+f"(c[2]), "+f"(c[3])
        : "r"(a0), "r"(a1), "r"(a2), "r"(a3), "r"(b0), "r"(b1));
}

__global__ void __launch_bounds__(256)
k_logits_mma(const float* __restrict__ bf, float* __restrict__ out) {
    extern __shared__ char smem[];
    uint32_t sb = smem_u32(smem);
    int tid = threadIdx.x, wid = tid >> 5, lane = tid & 31;
    int nb = blockIdx.x * 128;
    int wm = wid & 1;        // rows wm*32..+31 within 64-row tile
    int wn = wid >> 1;       // cols wn*32..+31 (0..3)

    // stage B once
    for (int idx = tid; idx < 1024; idx += 256) {
        int r = idx >> 3, c = idx & 7;
        uint32_t sw = SW128((uint32_t)(r * 128 + c * 16));
        size_t gb = (size_t)(nb + r) * 64 + c * 8;
        *(uint4*)(smem + S_BH + sw) = *(const uint4*)(g_wh + gb);
        *(uint4*)(smem + S_BL + sw) = *(const uint4*)(g_wl + gb);
    }

    // bias in regs (columns fixed for whole kernel)
    int g = lane >> 2, q4 = lane & 3;
    float2 bias_r[4];
#pragma unroll
    for (int nbk = 0; nbk < 4; nbk++)
        bias_r[nbk] = *(const float2*)(bf + nb + wn * 32 + nbk * 8 + 2 * q4);

    // prefetch A tile 0
    {
        uint32_t ab = sb + S_A;
#pragma unroll
        for (int it2 = 0; it2 < 2; it2++) {
            int idx = tid + it2 * 256;
            int r = idx >> 3, c = idx & 7;
            uint32_t sw = SW128((uint32_t)(r * 128 + c * 16));
            size_t go = (size_t)r * 64 + c * 8;
            cpa16(ab + sw,        g_yh + go);
            cpa16(ab + 8192 + sw, g_yl + go);
        }
    }
    CPA_COMMIT();
    __syncthreads();   // B visible

    int a_row  = wm * 32 + (lane & 15);
    int a_colb = (lane >> 4) * 16;
    int b_n    = wn * 32 + ((lane >> 3) >> 1) * 8 + (lane & 7);
    int b_kb   = ((lane >> 3) & 1) * 16;

    for (int it = 0; it < 50; it++) {
        int p = it & 1;
        // prefetch next tile into other buffer
        if (it + 1 < 50) {
            uint32_t ab = sb + S_A + (1 - p) * 16384;
#pragma unroll
            for (int it2 = 0; it2 < 2; it2++) {
                int idx = tid + it2 * 256;
                int r = idx >> 3, c = idx & 7;
                uint32_t sw = SW128((uint32_t)(r * 128 + c * 16));
                size_t go = (size_t)((it + 1) * 64 + r) * 64 + c * 8;
                cpa16(ab + sw,        g_yh + go);
                cpa16(ab + 8192 + sw, g_yl + go);
            }
        }
        CPA_COMMIT();
        CPA_WAIT1();       // A[it] complete
        __syncthreads();

        float c[2][4][4];
#pragma unroll
        for (int mb = 0; mb < 2; mb++)
#pragma unroll
            for (int nbk = 0; nbk < 4; nbk++)
#pragma unroll
                for (int j = 0; j < 4; j++) c[mb][nbk][j] = 0.f;

        uint32_t Ab = sb + S_A + p * 16384;
#pragma unroll
        for (int p3 = 0; p3 < 3; p3++) {
            uint32_t abase = Ab + ((p3 < 2) ? 0 : 8192);
            uint32_t bbase = sb + ((p3 == 1) ? S_BL : S_BH);
#pragma unroll
            for (int ks = 0; ks < 4; ks++) {
                uint32_t a0[4], a1[4];
                ldm4(a0[0], a0[1], a0[2], a0[3],
                     abase + SW128((uint32_t)(a_row * 128 + a_colb + ks * 32)));
                ldm4(a1[0], a1[1], a1[2], a1[3],
                     abase + SW128((uint32_t)((a_row + 16) * 128 + a_colb + ks * 32)));
#pragma unroll
                for (int q = 0; q < 2; q++) {
                    uint32_t b0, b1, b2, b3;
                    ldm4(b0, b1, b2, b3,
                         bbase + SW128((uint32_t)((b_n + q * 16) * 128 + b_kb + ks * 32)));
                    mma16816(c[0][2 * q],     a0[0], a0[1], a0[2], a0[3], b0, b1);
                    mma16816(c[0][2 * q + 1], a0[0], a0[1], a0[2], a0[3], b2, b3);
                    mma16816(c[1][2 * q],     a1[0], a1[1], a1[2], a1[3], b0, b1);
                    mma16816(c[1][2 * q + 1], a1[0], a1[1], a1[2], a1[3], b2, b3);
                }
            }
        }

        // epilogue for this row tile
#pragma unroll
        for (int mb = 0; mb < 2; mb++) {
            int row = it * 64 + wm * 32 + mb * 16 + g;
            float* orow = out + (size_t)row * NV;
#pragma unroll
            for (int nbk = 0; nbk < 4; nbk++) {
                int col = nb + wn * 32 + nbk * 8 + 2 * q4;
                float2 bv = bias_r[nbk];
                float2 v0 = make_float2(c[mb][nbk][0] + bv.x, c[mb][nbk][1] + bv.y);
                float2 v1 = make_float2(c[mb][nbk][2] + bv.x, c[mb][nbk][3] + bv.y);
                *(float2*)(orow + col)          = v0;
                *(float2*)(orow + 8 * NV + col) = v1;
            }
        }
        __syncthreads();   // protect buffer p before it is overwritten
    }
}

// ---------------------------------------------------------------------------
extern "C" void kernel_launch(void* const* d_in, const int* in_sizes, int n_in,
                              void* d_out, int out_size) {
    (void)in_sizes; (void)n_in; (void)out_size;
    const int*   x  = (const int*)d_in[0];
    const float* te = (const float*)d_in[1];
    const float* pe = (const float*)d_in[2];
    const float* Wq = (const float*)d_in[3];  const float* bq = (const float*)d_in[4];
    const float* Wk = (const float*)d_in[5];  const float* bk = (const float*)d_in[6];
    const float* Wv = (const float*)d_in[7];  const float* bv = (const float*)d_in[8];
    const float* Wo = (const float*)d_in[9];  const float* bo = (const float*)d_in[10];
    const float* W1 = (const float*)d_in[11]; const float* b1 = (const float*)d_in[12];
    const float* W2 = (const float*)d_in[13]; const float* b2 = (const float*)d_in[14];
    const float* Wf = (const float*)d_in[15]; const float* bf = (const float*)d_in[16];
    float* out = (float*)d_out;

    k_cvt_wf<<<NV / 64, 256>>>(Wf);
    k_qkv<<<dim3(B, H, 3), 128>>>(x, te, pe, Wq, bq, Wk, bk, Wv, bv);

    int attn_smem = A_TOTF * (int)sizeof(float);
    cudaFuncSetAttribute(k_attn, cudaFuncAttributeMaxDynamicSharedMemorySize, attn_smem);
    k_attn<<<dim3(B, H), 256, attn_smem>>>();

    int ffn_smem = F_TOTF * (int)sizeof(float);
    cudaFuncSetAttribute(k_ffn, cudaFuncAttributeMaxDynamicSharedMemorySize, ffn_smem);
    k_ffn<<<BT / 16, 256, ffn_smem>>>(Wo, bo, W1, b1, W2, b2);

    cudaFuncSetAttribute(k_logits_mma, cudaFuncAttributeMaxDynamicSharedMemorySize, S_TOT);
    k_logits_mma<<<NV / 128, 256, S_TOT>>>(bf, out);
}

// round 9
// speedup vs baseline: 1.2728x; 1.0481x over previous
#include <cuda_runtime.h>
#include <cuda_bf16.h>
#include <math.h>
#include <cstdint>

// ---------------------------------------------------------------------------
// SimpleGPT forward. R9: ffn at 3 blocks/SM (smem 63.5KB, weight-halves);
// logits shared-fragment mma loop. Rest from R8 (318us).
// B=64 T=50 V=32000 E=64 DH=128 H=8 M=256
// ---------------------------------------------------------------------------
constexpr int B   = 64;
constexpr int T   = 50;
constexpr int NV  = 32000;
constexpr int E   = 64;
constexpr int DH  = 128;
constexpr int H   = 8;
constexpr int FM  = 256;
constexpr int BT  = B * T;
constexpr int OD  = H * DH;

typedef unsigned long long u64;

__device__ __forceinline__ u64 ffma2(u64 a, u64 b, u64 c) {
    u64 d;
    asm("fma.rn.f32x2 %0, %1, %2, %3;" : "=l"(d) : "l"(a), "l"(b), "l"(c));
    return d;
}
__device__ __forceinline__ u64 bcast2(float x) {
    u64 d;
    unsigned xi = __float_as_uint(x);
    asm("mov.b64 %0, {%1, %1};" : "=l"(d) : "r"(xi));
    return d;
}
__device__ __forceinline__ u64 pack2f(float x, float y) {
    u64 d;
    unsigned xi = __float_as_uint(x), yi = __float_as_uint(y);
    asm("mov.b64 %0, {%1, %2};" : "=l"(d) : "r"(xi), "r"(yi));
    return d;
}
__device__ __forceinline__ u64 pk(uint32_t lo, uint32_t hi) {
    u64 d;
    asm("mov.b64 %0, {%1, %2};" : "=l"(d) : "r"(lo), "r"(hi));
    return d;
}
__device__ __forceinline__ float2 unpack2(u64 v) {
    unsigned lo, hi;
    asm("mov.b64 {%0, %1}, %2;" : "=r"(lo), "=r"(hi) : "l"(v));
    return make_float2(__uint_as_float(lo), __uint_as_float(hi));
}
__device__ __forceinline__ uint32_t smem_u32(const void* p) {
    uint32_t a;
    asm("{ .reg .u64 t; cvta.to.shared.u64 t, %1; cvt.u32.u64 %0, t; }" : "=r"(a) : "l"(p));
    return a;
}
__device__ __forceinline__ void cpa16(uint32_t saddr, const void* gptr) {
    asm volatile("cp.async.cg.shared.global [%0], [%1], 16;"
                 :: "r"(saddr), "l"(__cvta_generic_to_global(gptr)) : "memory");
}
#define CPA_COMMIT() asm volatile("cp.async.commit_group;" ::: "memory")
#define CPA_WAIT1()  asm volatile("cp.async.wait_group 1;" ::: "memory")
#define SW128(x) ((x) ^ (((x) >> 3) & 0x70))

// Scratch
__device__ __align__(16) float g_q[B * H * T * DH];
__device__ __align__(16) float g_k[B * H * T * DH];
__device__ __align__(16) float g_v[B * H * T * DH];
__device__ __align__(16) float g_o[BT * OD];
__device__ __align__(16) __nv_bfloat16 g_yh[BT * E];
__device__ __align__(16) __nv_bfloat16 g_yl[BT * E];
__device__ __align__(16) __nv_bfloat16 g_wh[(size_t)NV * E];
__device__ __align__(16) __nv_bfloat16 g_wl[(size_t)NV * E];

// ---------------------------------------------------------------------------
// 0) Wf -> transposed bf16 hi/lo
// ---------------------------------------------------------------------------
__global__ void k_cvt_wf(const float* __restrict__ Wf) {
    __shared__ float s[64 * 65];
    int tid = threadIdx.x;
    int nb = blockIdx.x * 64;
#pragma unroll
    for (int it = 0; it < 16; it++) {
        int i = tid + it * 256;
        int k = i >> 6, j = i & 63;
        s[k * 65 + j] = Wf[(size_t)k * NV + nb + j];
    }
    __syncthreads();
#pragma unroll
    for (int it = 0; it < 8; it++) {
        int i = tid + it * 256;
        int n = i >> 5, k2 = (i & 31) * 2;
        float v0 = s[k2 * 65 + n];
        float v1 = s[(k2 + 1) * 65 + n];
        __nv_bfloat16 h0 = __float2bfloat16_rn(v0);
        __nv_bfloat16 h1 = __float2bfloat16_rn(v1);
        __nv_bfloat162 hh; hh.x = h0; hh.y = h1;
        __nv_bfloat162 ll;
        ll.x = __float2bfloat16_rn(v0 - __bfloat162float(h0));
        ll.y = __float2bfloat16_rn(v1 - __bfloat162float(h1));
        size_t o = (size_t)(nb + n) * 64 + k2;
        *(__nv_bfloat162*)(g_wh + o) = hh;
        *(__nv_bfloat162*)(g_wl + o) = ll;
    }
}

// ---------------------------------------------------------------------------
// 1) QKV (+ fused embedding)
// ---------------------------------------------------------------------------
__global__ void k_qkv(const int* __restrict__ x,
                      const float* __restrict__ te, const float* __restrict__ pe,
                      const float* __restrict__ Wq, const float* __restrict__ bq,
                      const float* __restrict__ Wk, const float* __restrict__ bk,
                      const float* __restrict__ Wv, const float* __restrict__ bv) {
    __shared__ __align__(16) float h_s[T * E];
    int b = blockIdx.x, h = blockIdx.y, m = blockIdx.z;
    int d = threadIdx.x;

    for (int i = d; i < T * E; i += 128) {
        int t = i >> 6;
        h_s[i] = te[x[b * T + t] * E + (i & 63)] + pe[i];
    }

    const float* W    = (m == 0) ? Wq : ((m == 1) ? Wk : Wv);
    const float* bias = (m == 0) ? bq : ((m == 1) ? bk : bv);
    float* out = ((m == 0) ? g_q : ((m == 1) ? g_k : g_v)) + ((size_t)(b * H + h) * T) * DH;

    u64 wp[32];
#pragma unroll
    for (int e2 = 0; e2 < 32; e2++)
        wp[e2] = pack2f(W[(h * E + 2 * e2) * DH + d], W[(h * E + 2 * e2 + 1) * DH + d]);
    float bb = bias[h * DH + d];
    __syncthreads();

    for (int t = 0; t < T; t++) {
        u64 a0 = 0ull, a1 = 0ull;
        const u64* hp = (const u64*)(h_s + t * E);
#pragma unroll
        for (int e2 = 0; e2 < 32; e2 += 2) {
            a0 = ffma2(wp[e2],     hp[e2],     a0);
            a1 = ffma2(wp[e2 + 1], hp[e2 + 1], a1);
        }
        float2 s0 = unpack2(a0), s1 = unpack2(a1);
        out[t * DH + d] = s0.x + s0.y + s1.x + s1.y + bb;
    }
}

// ---------------------------------------------------------------------------
// 2) Attention (R6 version, validated)
// ---------------------------------------------------------------------------
constexpr int KP132 = 132;
constexpr int A_KOFF = T * KP132;
constexpr int A_VOFF = A_KOFF + T * DH;
constexpr int A_QOFF = A_VOFF;
constexpr int A_POFF = A_QOFF + 8 * 8 * DH;
constexpr int A_TOTF = A_POFF + 8 * 8 * 64;

__global__ void __launch_bounds__(256)
k_attn() {
    extern __shared__ float sm[];
    float* K_s = sm;
    float* V_s = sm + A_KOFF;
    float* q_s = sm + A_QOFF;
    float* p_s = sm + A_POFF;

    int b = blockIdx.x, h = blockIdx.y;
    int tid = threadIdx.x, w = tid >> 5, lane = tid & 31;
    size_t base = ((size_t)(b * H + h) * T) * DH;

    for (int i = tid; i < T * 32; i += 256) {
        int s = i >> 5, c4 = (i & 31) * 4;
        *(float4*)(K_s + s * KP132 + c4) = *(const float4*)(g_k + base + s * DH + c4);
        *(float4*)(V_s + s * DH + c4)    = *(const float4*)(g_v + base + s * DH + c4);
    }
    __syncthreads();

#pragma unroll
    for (int j = 0; j < 7; j++) {
        int t = w + 8 * j;
        if (t < T)
            *(float4*)(q_s + (w * 8 + j) * DH + lane * 4) =
                *(const float4*)(g_q + base + (size_t)t * DH + lane * 4);
    }
    __syncwarp();

    int s0 = lane, s1 = lane + 32;
    const float* k0p = K_s + s0 * KP132;
    const float* k1p = K_s + s1 * KP132;

    u64 acc[7][2];
#pragma unroll
    for (int j = 0; j < 7; j++) { acc[j][0] = 0ull; acc[j][1] = 0ull; }

#pragma unroll 8
    for (int c = 0; c < DH; c += 4) {
        uint4 k0 = *(const uint4*)(k0p + c);
        uint4 k1 = *(const uint4*)(k1p + c);
        u64 k0a = pk(k0.x, k0.y), k0b = pk(k0.z, k0.w);
        u64 k1a = pk(k1.x, k1.y), k1b = pk(k1.z, k1.w);
#pragma unroll
        for (int j = 0; j < 7; j++) {
            uint4 qv = *(const uint4*)(q_s + (w * 8 + j) * DH + c);
            u64 qa = pk(qv.x, qv.y), qb = pk(qv.z, qv.w);
            acc[j][0] = ffma2(qb, k0b, ffma2(qa, k0a, acc[j][0]));
            acc[j][1] = ffma2(qb, k1b, ffma2(qa, k1a, acc[j][1]));
        }
    }

    const float scale = 0.0883883476483184f;
    float sum[7], inv[7];
#pragma unroll
    for (int j = 0; j < 7; j++) {
        int t = w + 8 * j;
        bool valid = t < T;
        float2 f0 = unpack2(acc[j][0]);
        float2 f1 = unpack2(acc[j][1]);
        float sc0 = (f0.x + f0.y) * scale;
        float sc1 = (f1.x + f1.y) * scale;
        float e0 = (valid && s0 <= t) ? __expf(sc0) : 0.f;
        float e1 = (valid && s1 <= t) ? __expf(sc1) : 0.f;
        p_s[(w * 8 + j) * 64 + s0] = e0;
        p_s[(w * 8 + j) * 64 + s1] = e1;
        sum[j] = e0 + e1;
    }
#pragma unroll
    for (int off = 16; off; off >>= 1) {
#pragma unroll
        for (int j = 0; j < 7; j++)
            sum[j] += __shfl_xor_sync(0xffffffffu, sum[j], off);
    }
#pragma unroll
    for (int j = 0; j < 7; j++) inv[j] = 1.0f / sum[j];
    __syncwarp();

    u64 av[7][2];
#pragma unroll
    for (int j = 0; j < 7; j++) { av[j][0] = 0ull; av[j][1] = 0ull; }

    const float* vb = V_s + lane * 4;
    const float* pb = p_s + w * 8 * 64;
#pragma unroll 2
    for (int s = 0; s < T; s++) {
        uint4 vv = *(const uint4*)(vb + s * DH);
        u64 v01 = pk(vv.x, vv.y), v23 = pk(vv.z, vv.w);
#pragma unroll
        for (int j = 0; j < 7; j++) {
            u64 pj = bcast2(pb[j * 64 + s]);
            av[j][0] = ffma2(pj, v01, av[j][0]);
            av[j][1] = ffma2(pj, v23, av[j][1]);
        }
    }

#pragma unroll
    for (int j = 0; j < 7; j++) {
        int t = w + 8 * j;
        if (t < T) {
            float2 o01 = unpack2(av[j][0]), o23 = unpack2(av[j][1]);
            float4 ov = make_float4(o01.x * inv[j], o01.y * inv[j],
                                    o23.x * inv[j], o23.y * inv[j]);
            *(float4*)(g_o + (size_t)(b * T + t) * OD + h * DH + lane * 4) = ov;
        }
    }
}

// ---------------------------------------------------------------------------
// 3) Fused FFN v4: 16 rows/block, 63.5KB smem -> 3 blocks/SM.
//    W1/W2 consumed in 32KB halves from R1 (10240 floats).
// ---------------------------------------------------------------------------
constexpr int FR1   = 0;          // 10240 floats
constexpr int F_AS  = 10240;      // a: 16x64 = 1024
constexpr int F_MT  = 11264;      // m^T: 256x18 = 4608
constexpr int F_TOTF = 15872;     // 63488 B

__device__ __forceinline__ float gelu_exact(float x) {
    return 0.5f * x * (1.0f + erff(x * 0.70710678118654752f));
}

__global__ void __launch_bounds__(256)
k_ffn(const float* __restrict__ Wo, const float* __restrict__ bo,
      const float* __restrict__ W1, const float* __restrict__ b1,
      const float* __restrict__ W2, const float* __restrict__ b2) {
    extern __shared__ float sm[];
    float* R1   = sm + FR1;
    float* a_s  = sm + F_AS;
    float* m_sT = sm + F_MT;

    int tid = threadIdx.x;
    int rb  = blockIdx.x * 16;
    int e   = tid & 63;
    int rg  = tid >> 6;            // 0..3 -> rows rg*4..+3

    // Phase 1: a = o @ Wo + bo
    float* Wo_s = R1;              // 8192
    float* o_sT = R1 + 8192;       // 128 x 20 = 2560 (total 10752 > 10240? no: 2048 used, 16 rows pitch 20 = 2560)
    u64 acc0 = 0ull, acc1 = 0ull;
    for (int kt = 0; kt < OD; kt += 128) {
        for (int i = tid; i < 8192; i += 256) Wo_s[i] = Wo[kt * 64 + i];
        for (int i = tid; i < 2048; i += 256) {
            int k = i & 127, r = i >> 7;
            o_sT[k * 16 + r] = g_o[(size_t)(rb + r) * OD + kt + k];  // pitch 16 (rows=16)
        }
        __syncthreads();
#pragma unroll 4
        for (int k = 0; k < 128; k++) {
            u64 wv = bcast2(Wo_s[k * 64 + e]);
            const u64* op = (const u64*)(o_sT + k * 16 + rg * 4);
            acc0 = ffma2(wv, op[0], acc0);
            acc1 = ffma2(wv, op[1], acc1);
        }
        __syncthreads();
    }
    {
        float bov = bo[e];
        float2 c01 = unpack2(acc0), c23 = unpack2(acc1);
        a_s[(rg * 4 + 0) * 64 + e] = c01.x + bov;
        a_s[(rg * 4 + 1) * 64 + e] = c01.y + bov;
        a_s[(rg * 4 + 2) * 64 + e] = c23.x + bov;
        a_s[(rg * 4 + 3) * 64 + e] = c23.y + bov;
    }
    __syncthreads();

    // Phase 2: m^T = gelu(a @ W1 + b1), W1 in two column-halves of 128.
#pragma unroll
    for (int half = 0; half < 2; half++) {
        int jb = half * 128;
        for (int i = tid; i < 8192; i += 256) {
            int ee = i >> 7, jj = i & 127;
            R1[i] = W1[ee * FM + jb + jj];
        }
        __syncthreads();
        {
            int j2 = tid & 63;         // pair index within half (cols jb+2*j2, +1)
            int rh = tid >> 6;         // 0..3 -> rows rh*4..+3
            const u64* W1u = (const u64*)R1;   // [64][64] pairs
            u64 macc[4] = {0ull, 0ull, 0ull, 0ull};
#pragma unroll 4
            for (int ee = 0; ee < 64; ee++) {
                u64 wv = W1u[ee * 64 + j2];
#pragma unroll
                for (int i = 0; i < 4; i++)
                    macc[i] = ffma2(bcast2(a_s[(rh * 4 + i) * 64 + ee]), wv, macc[i]);
            }
            int jc = jb + 2 * j2;
            float bj0 = b1[jc], bj1 = b1[jc + 1];
#pragma unroll
            for (int i = 0; i < 4; i++) {
                int r = rh * 4 + i;
                float2 v = unpack2(macc[i]);
                m_sT[jc * 18 + r]       = gelu_exact(v.x + bj0);
                m_sT[(jc + 1) * 18 + r] = gelu_exact(v.y + bj1);
            }
        }
        __syncthreads();
    }

    // Phase 3: y = m @ W2 + b2 -> bf16 hi/lo. W2 in two row-halves of 128.
    u64 c0 = 0ull, c1 = 0ull;
#pragma unroll
    for (int half = 0; half < 2; half++) {
        int jb = half * 128;
        for (int i = tid; i < 8192; i += 256) R1[i] = W2[jb * 64 + i];
        __syncthreads();
#pragma unroll 4
        for (int j = 0; j < 128; j++) {
            u64 wv = bcast2(R1[j * 64 + e]);
            const u64* mp = (const u64*)(m_sT + (jb + j) * 18 + rg * 4);
            c0 = ffma2(wv, mp[0], c0);
            c1 = ffma2(wv, mp[1], c1);
        }
        __syncthreads();
    }
    {
        float b2v = b2[e];
        float2 d01 = unpack2(c0), d23 = unpack2(c1);
        float yv[4] = {d01.x + b2v, d01.y + b2v, d23.x + b2v, d23.y + b2v};
#pragma unroll
        for (int i = 0; i < 4; i++) {
            int r = rb + rg * 4 + i;
            __nv_bfloat16 hi = __float2bfloat16_rn(yv[i]);
            g_yh[r * 64 + e] = hi;
            g_yl[r * 64 + e] = __float2bfloat16_rn(yv[i] - __bfloat162float(hi));
        }
    }
}

// ---------------------------------------------------------------------------
// 4) Logits GEMM, persistent column-stripe (R8) + shared-fragment mma loop.
// ---------------------------------------------------------------------------
constexpr int S_BH = 0;
constexpr int S_BL = 16384;
constexpr int S_A  = 32768;
constexpr int S_TOT = 65536;

__device__ __forceinline__ void ldm4(uint32_t& r0, uint32_t& r1,
                                     uint32_t& r2, uint32_t& r3, uint32_t addr) {
    asm volatile("ldmatrix.sync.aligned.m8n8.x4.shared.b16 {%0,%1,%2,%3}, [%4];"
                 : "=r"(r0), "=r"(r1), "=r"(r2), "=r"(r3) : "r"(addr));
}
__device__ __forceinline__ void mma16816(float* c, const uint32_t* a,
                                         uint32_t b0, uint32_t b1) {
    asm volatile(
        "mma.sync.aligned.m16n8k16.row.col.f32.bf16.bf16.f32 "
        "{%0,%1,%2,%3}, {%4,%5,%6,%7}, {%8,%9}, {%0,%1,%2,%3};"
        : "+f"(c[0]), "+f"(c[1]), "+f"(c[2]), "+f"(c[3])
        : "r"(a[0]), "r"(a[1]), "r"(a[2]), "r"(a[3]), "r"(b0), "r"(b1));
}

__global__ void __launch_bounds__(256, 2)
k_logits_mma(const float* __restrict__ bf, float* __restrict__ out) {
    extern __shared__ char smem[];
    uint32_t sb = smem_u32(smem);
    int tid = threadIdx.x, wid = tid >> 5, lane = tid & 31;
    int nb = blockIdx.x * 128;
    int wm = wid & 1;
    int wn = wid >> 1;

    for (int idx = tid; idx < 1024; idx += 256) {
        int r = idx >> 3, c = idx & 7;
        uint32_t sw = SW128((uint32_t)(r * 128 + c * 16));
        size_t gb = (size_t)(nb + r) * 64 + c * 8;
        *(uint4*)(smem + S_BH + sw) = *(const uint4*)(g_wh + gb);
        *(uint4*)(smem + S_BL + sw) = *(const uint4*)(g_wl + gb);
    }

    int g = lane >> 2, q4 = lane & 3;
    float2 bias_r[4];
#pragma unroll
    for (int nbk = 0; nbk < 4; nbk++)
        bias_r[nbk] = *(const float2*)(bf + nb + wn * 32 + nbk * 8 + 2 * q4);

    {
        uint32_t ab = sb + S_A;
#pragma unroll
        for (int it2 = 0; it2 < 2; it2++) {
            int idx = tid + it2 * 256;
            int r = idx >> 3, c = idx & 7;
            uint32_t sw = SW128((uint32_t)(r * 128 + c * 16));
            size_t go = (size_t)r * 64 + c * 8;
            cpa16(ab + sw,        g_yh + go);
            cpa16(ab + 8192 + sw, g_yl + go);
        }
    }
    CPA_COMMIT();
    __syncthreads();

    int a_row  = wm * 32 + (lane & 15);
    int a_colb = (lane >> 4) * 16;
    int b_n    = wn * 32 + ((lane >> 3) >> 1) * 8 + (lane & 7);
    int b_kb   = ((lane >> 3) & 1) * 16;

    for (int it = 0; it < 50; it++) {
        int p = it & 1;
        if (it + 1 < 50) {
            uint32_t ab = sb + S_A + (1 - p) * 16384;
#pragma unroll
            for (int it2 = 0; it2 < 2; it2++) {
                int idx = tid + it2 * 256;
                int r = idx >> 3, c = idx & 7;
                uint32_t sw = SW128((uint32_t)(r * 128 + c * 16));
                size_t go = (size_t)((it + 1) * 64 + r) * 64 + c * 8;
                cpa16(ab + sw,        g_yh + go);
                cpa16(ab + 8192 + sw, g_yl + go);
            }
        }
        CPA_COMMIT();
        CPA_WAIT1();
        __syncthreads();

        float c[2][4][4];
#pragma unroll
        for (int mb = 0; mb < 2; mb++)
#pragma unroll
            for (int nbk = 0; nbk < 4; nbk++)
#pragma unroll
                for (int j = 0; j < 4; j++) c[mb][nbk][j] = 0.f;

        uint32_t Ah = sb + S_A + p * 16384;
        uint32_t Al = Ah + 8192;
        uint32_t Bh = sb + S_BH;
        uint32_t Bl = sb + S_BL;

#pragma unroll
        for (int ks = 0; ks < 4; ks++) {
            uint32_t swa0 = SW128((uint32_t)(a_row * 128 + a_colb + ks * 32));
            uint32_t swa1 = SW128((uint32_t)((a_row + 16) * 128 + a_colb + ks * 32));
            uint32_t swb0 = SW128((uint32_t)(b_n * 128 + b_kb + ks * 32));
            uint32_t swb1 = SW128((uint32_t)((b_n + 16) * 128 + b_kb + ks * 32));

            uint32_t ah0[4], ah1[4], al0[4], al1[4];
            uint32_t bh[8], bl[8];
            ldm4(ah0[0], ah0[1], ah0[2], ah0[3], Ah + swa0);
            ldm4(ah1[0], ah1[1], ah1[2], ah1[3], Ah + swa1);
            ldm4(al0[0], al0[1], al0[2], al0[3], Al + swa0);
            ldm4(al1[0], al1[1], al1[2], al1[3], Al + swa1);
            ldm4(bh[0], bh[1], bh[2], bh[3], Bh + swb0);
            ldm4(bh[4], bh[5], bh[6], bh[7], Bh + swb1);
            ldm4(bl[0], bl[1], bl[2], bl[3], Bl + swb0);
            ldm4(bl[4], bl[5], bl[6], bl[7], Bl + swb1);

#pragma unroll
            for (int q = 0; q < 2; q++) {
                // product 1: yh @ Wh
                mma16816(c[0][2 * q],     ah0, bh[4 * q],     bh[4 * q + 1]);
                mma16816(c[0][2 * q + 1], ah0, bh[4 * q + 2], bh[4 * q + 3]);
                mma16816(c[1][2 * q],     ah1, bh[4 * q],     bh[4 * q + 1]);
                mma16816(c[1][2 * q + 1], ah1, bh[4 * q + 2], bh[4 * q + 3]);
                // product 2: yh @ Wl
                mma16816(c[0][2 * q],     ah0, bl[4 * q],     bl[4 * q + 1]);
                mma16816(c[0][2 * q + 1], ah0, bl[4 * q + 2], bl[4 * q + 3]);
                mma16816(c[1][2 * q],     ah1, bl[4 * q],     bl[4 * q + 1]);
                mma16816(c[1][2 * q + 1], ah1, bl[4 * q + 2], bl[4 * q + 3]);
                // product 3: yl @ Wh
                mma16816(c[0][2 * q],     al0, bh[4 * q],     bh[4 * q + 1]);
                mma16816(c[0][2 * q + 1], al0, bh[4 * q + 2], bh[4 * q + 3]);
                mma16816(c[1][2 * q],     al1, bh[4 * q],     bh[4 * q + 1]);
                mma16816(c[1][2 * q + 1], al1, bh[4 * q + 2], bh[4 * q + 3]);
            }
        }

#pragma unroll
        for (int mb = 0; mb < 2; mb++) {
            int row = it * 64 + wm * 32 + mb * 16 + g;
            float* orow = out + (size_t)row * NV;
#pragma unroll
            for (int nbk = 0; nbk < 4; nbk++) {
                int col = nb + wn * 32 + nbk * 8 + 2 * q4;
                float2 bv = bias_r[nbk];
                float2 v0 = make_float2(c[mb][nbk][0] + bv.x, c[mb][nbk][1] + bv.y);
                float2 v1 = make_float2(c[mb][nbk][2] + bv.x, c[mb][nbk][3] + bv.y);
                *(float2*)(orow + col)          = v0;
                *(float2*)(orow + 8 * NV + col) = v1;
            }
        }
        __syncthreads();
    }
}

// ---------------------------------------------------------------------------
extern "C" void kernel_launch(void* const* d_in, const int* in_sizes, int n_in,
                              void* d_out, int out_size) {
    (void)in_sizes; (void)n_in; (void)out_size;
    const int*   x  = (const int*)d_in[0];
    const float* te = (const float*)d_in[1];
    const float* pe = (const float*)d_in[2];
    const float* Wq = (const float*)d_in[3];  const float* bq = (const float*)d_in[4];
    const float* Wk = (const float*)d_in[5];  const float* bk = (const float*)d_in[6];
    const float* Wv = (const float*)d_in[7];  const float* bv = (const float*)d_in[8];
    const float* Wo = (const float*)d_in[9];  const float* bo = (const float*)d_in[10];
    const float* W1 = (const float*)d_in[11]; const float* b1 = (const float*)d_in[12];
    const float* W2 = (const float*)d_in[13]; const float* b2 = (const float*)d_in[14];
    const float* Wf = (const float*)d_in[15]; const float* bf = (const float*)d_in[16];
    float* out = (float*)d_out;

    k_cvt_wf<<<NV / 64, 256>>>(Wf);
    k_qkv<<<dim3(B, H, 3), 128>>>(x, te, pe, Wq, bq, Wk, bk, Wv, bv);

    int attn_smem = A_TOTF * (int)sizeof(float);
    cudaFuncSetAttribute(k_attn, cudaFuncAttributeMaxDynamicSharedMemorySize, attn_smem);
    k_attn<<<dim3(B, H), 256, attn_smem>>>();

    int ffn_smem = F_TOTF * (int)sizeof(float);    // 63.5 KB -> 3 blocks/SM
    cudaFuncSetAttribute(k_ffn, cudaFuncAttributeMaxDynamicSharedMemorySize, ffn_smem);
    k_ffn<<<BT / 16, 256, ffn_smem>>>(Wo, bo, W1, b1, W2, b2);

    cudaFuncSetAttribute(k_logits_mma, cudaFuncAttributeMaxDynamicSharedMemorySize, S_TOT);
    k_logits_mma<<<NV / 128, 256, S_TOT>>>(bf, out);
}

// round 13
// speedup vs baseline: 1.3367x; 1.0502x over previous
#include <cuda_runtime.h>
#include <cuda_bf16.h>
#include <math.h>
#include <cstdint>

// ---------------------------------------------------------------------------
// SimpleGPT forward. R13: fixes R10-R12 root cause — __device__ globals were
// passed as kernel args FROM HOST CODE (garbage pointers -> fault -> sticky
// context -> zero output). k_cvt_t now selects output arrays in device code.
// FFN on tensor cores (2-term bf16 split); logits/attn/qkv from R9.
// B=64 T=50 V=32000 E=64 DH=128 H=8 M=256
// ---------------------------------------------------------------------------
constexpr int B   = 64;
constexpr int T   = 50;
constexpr int NV  = 32000;
constexpr int E   = 64;
constexpr int DH  = 128;
constexpr int H   = 8;
constexpr int FM  = 256;
constexpr int BT  = B * T;
constexpr int OD  = H * DH;

typedef unsigned long long u64;

__device__ __forceinline__ u64 ffma2(u64 a, u64 b, u64 c) {
    u64 d;
    asm("fma.rn.f32x2 %0, %1, %2, %3;" : "=l"(d) : "l"(a), "l"(b), "l"(c));
    return d;
}
__device__ __forceinline__ u64 bcast2(float x) {
    u64 d;
    unsigned xi = __float_as_uint(x);
    asm("mov.b64 %0, {%1, %1};" : "=l"(d) : "r"(xi));
    return d;
}
__device__ __forceinline__ u64 pack2f(float x, float y) {
    u64 d;
    unsigned xi = __float_as_uint(x), yi = __float_as_uint(y);
    asm("mov.b64 %0, {%1, %2};" : "=l"(d) : "r"(xi), "r"(yi));
    return d;
}
__device__ __forceinline__ u64 pk(uint32_t lo, uint32_t hi) {
    u64 d;
    asm("mov.b64 %0, {%1, %2};" : "=l"(d) : "r"(lo), "r"(hi));
    return d;
}
__device__ __forceinline__ float2 unpack2(u64 v) {
    unsigned lo, hi;
    asm("mov.b64 {%0, %1}, %2;" : "=r"(lo), "=r"(hi) : "l"(v));
    return make_float2(__uint_as_float(lo), __uint_as_float(hi));
}
__device__ __forceinline__ uint32_t smem_u32(const void* p) {
    uint32_t a;
    asm("{ .reg .u64 t; cvta.to.shared.u64 t, %1; cvt.u32.u64 %0, t; }" : "=r"(a) : "l"(p));
    return a;
}
__device__ __forceinline__ void cpa16(uint32_t saddr, const void* gptr) {
    asm volatile("cp.async.cg.shared.global [%0], [%1], 16;"
                 :: "r"(saddr), "l"(__cvta_generic_to_global(gptr)) : "memory");
}
#define CPA_COMMIT() asm volatile("cp.async.commit_group;" ::: "memory")
#define CPA_WAIT1()  asm volatile("cp.async.wait_group 1;" ::: "memory")
#define SW128(x) ((x) ^ (((x) >> 3) & 0x70))

__device__ __forceinline__ float gelu_exact(float x) {
    return 0.5f * x * (1.0f + erff(x * 0.70710678118654752f));
}
__device__ __forceinline__ void split2(float v0, float v1,
                                       __nv_bfloat162& hh, __nv_bfloat162& ll) {
    __nv_bfloat16 h0 = __float2bfloat16_rn(v0);
    __nv_bfloat16 h1 = __float2bfloat16_rn(v1);
    hh.x = h0; hh.y = h1;
    ll.x = __float2bfloat16_rn(v0 - __bfloat162float(h0));
    ll.y = __float2bfloat16_rn(v1 - __bfloat162float(h1));
}

// Scratch (device globals — referenced ONLY from device code)
__device__ __align__(16) float g_q[B * H * T * DH];
__device__ __align__(16) float g_k[B * H * T * DH];
__device__ __align__(16) float g_v[B * H * T * DH];
__device__ __align__(16) __nv_bfloat16 g_oh[BT * OD];
__device__ __align__(16) __nv_bfloat16 g_ol[BT * OD];
__device__ __align__(16) __nv_bfloat16 g_ah[BT * E];
__device__ __align__(16) __nv_bfloat16 g_al[BT * E];
__device__ __align__(16) __nv_bfloat16 g_yh[BT * E];
__device__ __align__(16) __nv_bfloat16 g_yl[BT * E];
__device__ __align__(16) __nv_bfloat16 g_wh[(size_t)NV * E];
__device__ __align__(16) __nv_bfloat16 g_wl[(size_t)NV * E];
__device__ __align__(16) __nv_bfloat16 g_woTh[OD * E];   // [64 n][1024 k]
__device__ __align__(16) __nv_bfloat16 g_woTl[OD * E];
__device__ __align__(16) __nv_bfloat16 g_w1Th[FM * E];   // [256 n][64 k]
__device__ __align__(16) __nv_bfloat16 g_w1Tl[FM * E];
__device__ __align__(16) __nv_bfloat16 g_w2Th[E * FM];   // [64 n][256 k]
__device__ __align__(16) __nv_bfloat16 g_w2Tl[E * FM];

// ---------------------------------------------------------------------------
// 0a) Wf -> transposed bf16 hi/lo
// ---------------------------------------------------------------------------
__global__ void k_cvt_wf(const float* __restrict__ Wf) {
    __shared__ float s[64 * 65];
    int tid = threadIdx.x;
    int nb = blockIdx.x * 64;
#pragma unroll
    for (int it = 0; it < 16; it++) {
        int i = tid + it * 256;
        int k = i >> 6, j = i & 63;
        s[k * 65 + j] = Wf[(size_t)k * NV + nb + j];
    }
    __syncthreads();
#pragma unroll
    for (int it = 0; it < 8; it++) {
        int i = tid + it * 256;
        int n = i >> 5, k2 = (i & 31) * 2;
        __nv_bfloat162 hh, ll;
        split2(s[k2 * 65 + n], s[(k2 + 1) * 65 + n], hh, ll);
        size_t o = (size_t)(nb + n) * 64 + k2;
        *(__nv_bfloat162*)(g_wh + o) = hh;
        *(__nv_bfloat162*)(g_wl + o) = ll;
    }
}

// ---------------------------------------------------------------------------
// 0b) Transpose+split in[R][C] fp32 -> [C][R] bf16 hi/lo. Output arrays
//     selected IN DEVICE CODE via `which` (0=Wo, 1=W1, 2=W2).
// ---------------------------------------------------------------------------
__global__ void k_cvt_t(const float* __restrict__ in, int R, int C, int which) {
    __shared__ float s[64 * 65];
    int tid = threadIdx.x;
    int cb = blockIdx.x * 64, rb = blockIdx.y * 64;

    __nv_bfloat16* oh;
    __nv_bfloat16* ol;
    if (which == 0)      { oh = g_woTh; ol = g_woTl; }
    else if (which == 1) { oh = g_w1Th; ol = g_w1Tl; }
    else                 { oh = g_w2Th; ol = g_w2Tl; }

#pragma unroll
    for (int it = 0; it < 16; it++) {
        int i = tid + it * 256;
        int r = i >> 6, c = i & 63;
        s[r * 65 + c] = in[(size_t)(rb + r) * C + cb + c];
    }
    __syncthreads();
#pragma unroll
    for (int it = 0; it < 8; it++) {
        int i = tid + it * 256;
        int n = i >> 5, k2 = (i & 31) * 2;
        __nv_bfloat162 hh, ll;
        split2(s[k2 * 65 + n], s[(k2 + 1) * 65 + n], hh, ll);
        size_t o = (size_t)(cb + n) * R + rb + k2;
        *(__nv_bfloat162*)(oh + o) = hh;
        *(__nv_bfloat162*)(ol + o) = ll;
    }
}

// ---------------------------------------------------------------------------
// 1) QKV (+ fused embedding)
// ---------------------------------------------------------------------------
__global__ void k_qkv(const int* __restrict__ x,
                      const float* __restrict__ te, const float* __restrict__ pe,
                      const float* __restrict__ Wq, const float* __restrict__ bq,
                      const float* __restrict__ Wk, const float* __restrict__ bk,
                      const float* __restrict__ Wv, const float* __restrict__ bv) {
    __shared__ __align__(16) float h_s[T * E];
    int b = blockIdx.x, h = blockIdx.y, m = blockIdx.z;
    int d = threadIdx.x;

    for (int i = d; i < T * E; i += 128) {
        int t = i >> 6;
        h_s[i] = te[x[b * T + t] * E + (i & 63)] + pe[i];
    }

    const float* W    = (m == 0) ? Wq : ((m == 1) ? Wk : Wv);
    const float* bias = (m == 0) ? bq : ((m == 1) ? bk : bv);
    float* out = ((m == 0) ? g_q : ((m == 1) ? g_k : g_v)) + ((size_t)(b * H + h) * T) * DH;

    u64 wp[32];
#pragma unroll
    for (int e2 = 0; e2 < 32; e2++)
        wp[e2] = pack2f(W[(h * E + 2 * e2) * DH + d], W[(h * E + 2 * e2 + 1) * DH + d]);
    float bb = bias[h * DH + d];
    __syncthreads();

    for (int t = 0; t < T; t++) {
        u64 a0 = 0ull, a1 = 0ull;
        const u64* hp = (const u64*)(h_s + t * E);
#pragma unroll
        for (int e2 = 0; e2 < 32; e2 += 2) {
            a0 = ffma2(wp[e2],     hp[e2],     a0);
            a1 = ffma2(wp[e2 + 1], hp[e2 + 1], a1);
        }
        float2 s0 = unpack2(a0), s1 = unpack2(a1);
        out[t * DH + d] = s0.x + s0.y + s1.x + s1.y + bb;
    }
}

// ---------------------------------------------------------------------------
// 2) Attention (R6 core; epilogue emits bf16 hi/lo o)
// ---------------------------------------------------------------------------
constexpr int KP132 = 132;
constexpr int A_KOFF = T * KP132;
constexpr int A_VOFF = A_KOFF + T * DH;
constexpr int A_QOFF = A_VOFF;
constexpr int A_POFF = A_QOFF + 8 * 8 * DH;
constexpr int A_TOTF = A_POFF + 8 * 8 * 64;

__global__ void __launch_bounds__(256)
k_attn() {
    extern __shared__ float sm[];
    float* K_s = sm;
    float* V_s = sm + A_KOFF;
    float* q_s = sm + A_QOFF;
    float* p_s = sm + A_POFF;

    int b = blockIdx.x, h = blockIdx.y;
    int tid = threadIdx.x, w = tid >> 5, lane = tid & 31;
    size_t base = ((size_t)(b * H + h) * T) * DH;

    for (int i = tid; i < T * 32; i += 256) {
        int s = i >> 5, c4 = (i & 31) * 4;
        *(float4*)(K_s + s * KP132 + c4) = *(const float4*)(g_k + base + s * DH + c4);
        *(float4*)(V_s + s * DH + c4)    = *(const float4*)(g_v + base + s * DH + c4);
    }
    __syncthreads();

#pragma unroll
    for (int j = 0; j < 7; j++) {
        int t = w + 8 * j;
        if (t < T)
            *(float4*)(q_s + (w * 8 + j) * DH + lane * 4) =
                *(const float4*)(g_q + base + (size_t)t * DH + lane * 4);
    }
    __syncwarp();

    int s0 = lane, s1 = lane + 32;
    const float* k0p = K_s + s0 * KP132;
    const float* k1p = K_s + s1 * KP132;

    u64 acc[7][2];
#pragma unroll
    for (int j = 0; j < 7; j++) { acc[j][0] = 0ull; acc[j][1] = 0ull; }

#pragma unroll 8
    for (int c = 0; c < DH; c += 4) {
        uint4 k0 = *(const uint4*)(k0p + c);
        uint4 k1 = *(const uint4*)(k1p + c);
        u64 k0a = pk(k0.x, k0.y), k0b = pk(k0.z, k0.w);
        u64 k1a = pk(k1.x, k1.y), k1b = pk(k1.z, k1.w);
#pragma unroll
        for (int j = 0; j < 7; j++) {
            uint4 qv = *(const uint4*)(q_s + (w * 8 + j) * DH + c);
            u64 qa = pk(qv.x, qv.y), qb = pk(qv.z, qv.w);
            acc[j][0] = ffma2(qb, k0b, ffma2(qa, k0a, acc[j][0]));
            acc[j][1] = ffma2(qb, k1b, ffma2(qa, k1a, acc[j][1]));
        }
    }

    const float scale = 0.0883883476483184f;
    float sum[7], inv[7];
#pragma unroll
    for (int j = 0; j < 7; j++) {
        int t = w + 8 * j;
        bool valid = t < T;
        float2 f0 = unpack2(acc[j][0]);
        float2 f1 = unpack2(acc[j][1]);
        float sc0 = (f0.x + f0.y) * scale;
        float sc1 = (f1.x + f1.y) * scale;
        float e0 = (valid && s0 <= t) ? __expf(sc0) : 0.f;
        float e1 = (valid && s1 <= t) ? __expf(sc1) : 0.f;
        p_s[(w * 8 + j) * 64 + s0] = e0;
        p_s[(w * 8 + j) * 64 + s1] = e1;
        sum[j] = e0 + e1;
    }
#pragma unroll
    for (int off = 16; off; off >>= 1) {
#pragma unroll
        for (int j = 0; j < 7; j++)
            sum[j] += __shfl_xor_sync(0xffffffffu, sum[j], off);
    }
#pragma unroll
    for (int j = 0; j < 7; j++) inv[j] = 1.0f / sum[j];
    __syncwarp();

    u64 av[7][2];
#pragma unroll
    for (int j = 0; j < 7; j++) { av[j][0] = 0ull; av[j][1] = 0ull; }

    const float* vb = V_s + lane * 4;
    const float* pb = p_s + w * 8 * 64;
#pragma unroll 2
    for (int s = 0; s < T; s++) {
        uint4 vv = *(const uint4*)(vb + s * DH);
        u64 v01 = pk(vv.x, vv.y), v23 = pk(vv.z, vv.w);
#pragma unroll
        for (int j = 0; j < 7; j++) {
            u64 pj = bcast2(pb[j * 64 + s]);
            av[j][0] = ffma2(pj, v01, av[j][0]);
            av[j][1] = ffma2(pj, v23, av[j][1]);
        }
    }

#pragma unroll
    for (int j = 0; j < 7; j++) {
        int t = w + 8 * j;
        if (t < T) {
            float2 o01 = unpack2(av[j][0]), o23 = unpack2(av[j][1]);
            __nv_bfloat162 hA, lA, hB, lB;
            split2(o01.x * inv[j], o01.y * inv[j], hA, lA);
            split2(o23.x * inv[j], o23.y * inv[j], hB, lB);
            size_t o = (size_t)(b * T + t) * OD + h * DH + lane * 4;
            *(__nv_bfloat162*)(g_oh + o)     = hA;
            *(__nv_bfloat162*)(g_oh + o + 2) = hB;
            *(__nv_bfloat162*)(g_ol + o)     = lA;
            *(__nv_bfloat162*)(g_ol + o + 2) = lB;
        }
    }
}

// ---------------------------------------------------------------------------
// mma.sync helpers
// ---------------------------------------------------------------------------
__device__ __forceinline__ void ldm4(uint32_t& r0, uint32_t& r1,
                                     uint32_t& r2, uint32_t& r3, uint32_t addr) {
    asm volatile("ldmatrix.sync.aligned.m8n8.x4.shared.b16 {%0,%1,%2,%3}, [%4];"
                 : "=r"(r0), "=r"(r1), "=r"(r2), "=r"(r3) : "r"(addr));
}
__device__ __forceinline__ void mma16816(float* c, const uint32_t* a,
                                         uint32_t b0, uint32_t b1) {
    asm volatile(
        "mma.sync.aligned.m16n8k16.row.col.f32.bf16.bf16.f32 "
        "{%0,%1,%2,%3}, {%4,%5,%6,%7}, {%8,%9}, {%0,%1,%2,%3};"
        : "+f"(c[0]), "+f"(c[1]), "+f"(c[2]), "+f"(c[3])
        : "r"(a[0]), "r"(a[1]), "r"(a[2]), "r"(a[3]), "r"(b0), "r"(b1));
}

// ---------------------------------------------------------------------------
// 3a) FFN stage A: a = o @ Wo + bo -> bf16 hi/lo. 32 rows/block (grid 100),
//     24KB static smem, synchronous staging.
// ---------------------------------------------------------------------------
__global__ void __launch_bounds__(256)
k_ffn_a(const float* __restrict__ bo) {
    __shared__ __align__(16) char smem[24576];   // A hi 4K | A lo 4K | B hi 8K | B lo 8K
    uint32_t sb = smem_u32(smem);
    int tid = threadIdx.x, wid = tid >> 5, lane = tid & 31;
    int rb = blockIdx.x * 32;
    int wm = wid & 1;
    int wn = wid >> 1;

    int g = lane >> 2, q4 = lane & 3;
    int a_row  = wm * 16 + (lane & 15);
    int a_colb = (lane >> 4) * 16;
    int b_n    = wn * 16 + ((lane >> 3) >> 1) * 8 + (lane & 7);
    int b_kb   = ((lane >> 3) & 1) * 16;

    float cA[2][4];
#pragma unroll
    for (int q = 0; q < 2; q++)
#pragma unroll
        for (int j = 0; j < 4; j++) cA[q][j] = 0.f;

    for (int kc = 0; kc < 16; kc++) {
        for (int i = tid; i < 512; i += 256) {
            int half = i >> 8, r = (i >> 3) & 31, c = i & 7;
            uint32_t sw = SW128((uint32_t)(r * 128 + c * 16));
            const __nv_bfloat16* src =
                (half ? g_ol : g_oh) + (size_t)(rb + r) * OD + kc * 64 + c * 8;
            *(uint4*)(smem + half * 4096 + sw) = *(const uint4*)src;
        }
        for (int i = tid; i < 1024; i += 256) {
            int half = i >> 9, n = (i >> 3) & 63, c = i & 7;
            uint32_t sw = SW128((uint32_t)(n * 128 + c * 16));
            const __nv_bfloat16* src =
                (half ? g_woTl : g_woTh) + (size_t)n * OD + kc * 64 + c * 8;
            *(uint4*)(smem + 8192 + half * 8192 + sw) = *(const uint4*)src;
        }
        __syncthreads();

        uint32_t Ah = sb, Al = sb + 4096, Bh = sb + 8192, Bl = sb + 16384;
#pragma unroll
        for (int ks = 0; ks < 4; ks++) {
            uint32_t swa = SW128((uint32_t)(a_row * 128 + a_colb + ks * 32));
            uint32_t swb = SW128((uint32_t)(b_n * 128 + b_kb + ks * 32));
            uint32_t ah[4], al[4], bh[4], bl[4];
            ldm4(ah[0], ah[1], ah[2], ah[3], Ah + swa);
            ldm4(al[0], al[1], al[2], al[3], Al + swa);
            ldm4(bh[0], bh[1], bh[2], bh[3], Bh + swb);
            ldm4(bl[0], bl[1], bl[2], bl[3], Bl + swb);
#pragma unroll
            for (int q = 0; q < 2; q++) {
                mma16816(cA[q], ah, bh[2 * q], bh[2 * q + 1]);
                mma16816(cA[q], ah, bl[2 * q], bl[2 * q + 1]);
                mma16816(cA[q], al, bh[2 * q], bh[2 * q + 1]);
            }
        }
        __syncthreads();
    }

#pragma unroll
    for (int q = 0; q < 2; q++) {
        int col = wn * 16 + q * 8 + 2 * q4;
        float b0 = bo[col], b1v = bo[col + 1];
        int r0 = rb + wm * 16 + g, r1 = r0 + 8;
        __nv_bfloat162 hh0, ll0, hh1, ll1;
        split2(cA[q][0] + b0, cA[q][1] + b1v, hh0, ll0);
        split2(cA[q][2] + b0, cA[q][3] + b1v, hh1, ll1);
        *(__nv_bfloat162*)(g_ah + r0 * 64 + col) = hh0;
        *(__nv_bfloat162*)(g_al + r0 * 64 + col) = ll0;
        *(__nv_bfloat162*)(g_ah + r1 * 64 + col) = hh1;
        *(__nv_bfloat162*)(g_al + r1 * 64 + col) = ll1;
    }
}

// ---------------------------------------------------------------------------
// 3b) FFN stage B+C: m = gelu(a@W1+b1); y = m@W2+b2 -> bf16 hi/lo.
//     32 rows/block (grid 100), 72KB smem. W1T in halves, W2T in pairs.
// ---------------------------------------------------------------------------
constexpr int FB_W = 0;        // 32768
constexpr int FB_A = 32768;    // 8192
constexpr int FB_M = 40960;    // 32768
constexpr int FB_TOT = 73728;  // 72KB

__global__ void __launch_bounds__(256)
k_ffn_b(const float* __restrict__ b1, const float* __restrict__ b2) {
    extern __shared__ char smem[];
    uint32_t sb = smem_u32(smem);
    int tid = threadIdx.x, wid = tid >> 5, lane = tid & 31;
    int rb = blockIdx.x * 32;
    int wm = wid & 1;
    int wn = wid >> 1;

    int g = lane >> 2, q4 = lane & 3;
    int a_row  = wm * 16 + (lane & 15);
    int a_colb = (lane >> 4) * 16;
    int bn_sub = ((lane >> 3) >> 1) * 8 + (lane & 7);
    int b_kb   = ((lane >> 3) & 1) * 16;

    for (int i = tid; i < 512; i += 256) {
        int half = i >> 8, r = (i >> 3) & 31, c = i & 7;
        uint32_t sw = SW128((uint32_t)(r * 128 + c * 16));
        const __nv_bfloat16* src =
            (half ? g_al : g_ah) + (size_t)(rb + r) * 64 + c * 8;
        *(uint4*)(smem + FB_A + half * 4096 + sw) = *(const uint4*)src;
    }

    // ---- Phase B: m = gelu(a @ W1 + b1), W1T in two 128-col halves --------
    for (int half = 0; half < 2; half++) {
        for (int i = tid; i < 2048; i += 256) {
            int hl = i >> 10;
            int idx = i & 1023;
            int nl = idx >> 3, c = idx & 7;
            uint32_t sw = SW128((uint32_t)(nl * 128 + c * 16));
            const __nv_bfloat16* src = (hl ? g_w1Tl : g_w1Th)
                + (size_t)(half * 128 + nl) * 64 + c * 8;
            *(uint4*)(smem + FB_W + hl * 16384 + sw) = *(const uint4*)src;
        }
        __syncthreads();

        float c2f[4][4];
#pragma unroll
        for (int i = 0; i < 4; i++)
#pragma unroll
            for (int j = 0; j < 4; j++) c2f[i][j] = 0.f;

        uint32_t Ah = sb + FB_A, Al = Ah + 4096;
        uint32_t Bh = sb + FB_W, Bl = Bh + 16384;
#pragma unroll
        for (int ks = 0; ks < 4; ks++) {
            uint32_t swa = SW128((uint32_t)(a_row * 128 + a_colb + ks * 32));
            uint32_t ah[4], al[4];
            ldm4(ah[0], ah[1], ah[2], ah[3], Ah + swa);
            ldm4(al[0], al[1], al[2], al[3], Al + swa);
#pragma unroll
            for (int nb2 = 0; nb2 < 2; nb2++) {
                int rowl = wn * 32 + nb2 * 16 + bn_sub;
                uint32_t swb = SW128((uint32_t)(rowl * 128 + b_kb + ks * 32));
                uint32_t bh[4], bl[4];
                ldm4(bh[0], bh[1], bh[2], bh[3], Bh + swb);
                ldm4(bl[0], bl[1], bl[2], bl[3], Bl + swb);
#pragma unroll
                for (int q = 0; q < 2; q++) {
                    mma16816(c2f[2 * nb2 + q], ah, bh[2 * q], bh[2 * q + 1]);
                    mma16816(c2f[2 * nb2 + q], ah, bl[2 * q], bl[2 * q + 1]);
                    mma16816(c2f[2 * nb2 + q], al, bh[2 * q], bh[2 * q + 1]);
                }
            }
        }

#pragma unroll
        for (int nb2 = 0; nb2 < 2; nb2++) {
#pragma unroll
            for (int q = 0; q < 2; q++) {
                int col = half * 128 + wn * 32 + nb2 * 16 + q * 8 + 2 * q4;
                float bj0 = b1[col], bj1 = b1[col + 1];
                int chunk = col >> 6, k2 = col & 63;
                const float* cf = c2f[2 * nb2 + q];
                __nv_bfloat162 hh0, ll0, hh1, ll1;
                split2(gelu_exact(cf[0] + bj0), gelu_exact(cf[1] + bj1), hh0, ll0);
                split2(gelu_exact(cf[2] + bj0), gelu_exact(cf[3] + bj1), hh1, ll1);
                uint32_t coff = (uint32_t)(FB_M + chunk * 8192);
                uint32_t sw0 = SW128((uint32_t)((wm * 16 + g) * 128 + k2 * 2));
                uint32_t sw1 = SW128((uint32_t)((wm * 16 + g + 8) * 128 + k2 * 2));
                *(__nv_bfloat162*)(smem + coff + sw0)        = hh0;
                *(__nv_bfloat162*)(smem + coff + 4096 + sw0) = ll0;
                *(__nv_bfloat162*)(smem + coff + sw1)        = hh1;
                *(__nv_bfloat162*)(smem + coff + 4096 + sw1) = ll1;
            }
        }
        __syncthreads();
    }

    // ---- Phase C: y = m @ W2 + b2, W2T in two chunk-pairs -----------------
    float cC[2][4];
#pragma unroll
    for (int q = 0; q < 2; q++)
#pragma unroll
        for (int j = 0; j < 4; j++) cC[q][j] = 0.f;

    int b_n = wn * 16 + bn_sub;
    for (int pair = 0; pair < 2; pair++) {
        for (int i = tid; i < 2048; i += 256) {
            int cl = i >> 10;
            int rest = i & 1023;
            int hl = rest >> 9;
            int idx = rest & 511;
            int n = idx >> 3, c = idx & 7;
            uint32_t sw = SW128((uint32_t)(n * 128 + c * 16));
            const __nv_bfloat16* src = (hl ? g_w2Tl : g_w2Th)
                + (size_t)n * FM + (2 * pair + cl) * 64 + c * 8;
            *(uint4*)(smem + FB_W + cl * 16384 + hl * 8192 + sw) = *(const uint4*)src;
        }
        __syncthreads();

#pragma unroll
        for (int cl = 0; cl < 2; cl++) {
            int chunk = 2 * pair + cl;
            uint32_t Ah = sb + FB_M + chunk * 8192, Al = Ah + 4096;
            uint32_t Bh = sb + FB_W + cl * 16384,   Bl = Bh + 8192;
#pragma unroll
            for (int ks = 0; ks < 4; ks++) {
                uint32_t swa = SW128((uint32_t)(a_row * 128 + a_colb + ks * 32));
                uint32_t swb = SW128((uint32_t)(b_n * 128 + b_kb + ks * 32));
                uint32_t ah[4], al[4], bh[4], bl[4];
                ldm4(ah[0], ah[1], ah[2], ah[3], Ah + swa);
                ldm4(al[0], al[1], al[2], al[3], Al + swa);
                ldm4(bh[0], bh[1], bh[2], bh[3], Bh + swb);
                ldm4(bl[0], bl[1], bl[2], bl[3], Bl + swb);
#pragma unroll
                for (int q = 0; q < 2; q++) {
                    mma16816(cC[q], ah, bh[2 * q], bh[2 * q + 1]);
                    mma16816(cC[q], ah, bl[2 * q], bl[2 * q + 1]);
                    mma16816(cC[q], al, bh[2 * q], bh[2 * q + 1]);
                }
            }
        }
        __syncthreads();
    }

#pragma unroll
    for (int q = 0; q < 2; q++) {
        int col = wn * 16 + q * 8 + 2 * q4;
        float b20 = b2[col], b21 = b2[col + 1];
        int r0 = rb + wm * 16 + g, r1 = r0 + 8;
        __nv_bfloat162 hh0, ll0, hh1, ll1;
        split2(cC[q][0] + b20, cC[q][1] + b21, hh0, ll0);
        split2(cC[q][2] + b20, cC[q][3] + b21, hh1, ll1);
        *(__nv_bfloat162*)(g_yh + r0 * 64 + col) = hh0;
        *(__nv_bfloat162*)(g_yl + r0 * 64 + col) = ll0;
        *(__nv_bfloat162*)(g_yh + r1 * 64 + col) = hh1;
        *(__nv_bfloat162*)(g_yl + r1 * 64 + col) = ll1;
    }
}

// ---------------------------------------------------------------------------
// 4) Logits GEMM (R9 version, validated)
// ---------------------------------------------------------------------------
constexpr int S_BH = 0;
constexpr int S_BL = 16384;
constexpr int S_A  = 32768;
constexpr int S_TOT = 65536;

__global__ void __launch_bounds__(256, 2)
k_logits_mma(const float* __restrict__ bf, float* __restrict__ out) {
    extern __shared__ char smem[];
    uint32_t sb = smem_u32(smem);
    int tid = threadIdx.x, wid = tid >> 5, lane = tid & 31;
    int nb = blockIdx.x * 128;
    int wm = wid & 1;
    int wn = wid >> 1;

    for (int idx = tid; idx < 1024; idx += 256) {
        int r = idx >> 3, c = idx & 7;
        uint32_t sw = SW128((uint32_t)(r * 128 + c * 16));
        size_t gb = (size_t)(nb + r) * 64 + c * 8;
        *(uint4*)(smem + S_BH + sw) = *(const uint4*)(g_wh + gb);
        *(uint4*)(smem + S_BL + sw) = *(const uint4*)(g_wl + gb);
    }

    int g = lane >> 2, q4 = lane & 3;
    float2 bias_r[4];
#pragma unroll
    for (int nbk = 0; nbk < 4; nbk++)
        bias_r[nbk] = *(const float2*)(bf + nb + wn * 32 + nbk * 8 + 2 * q4);

    {
        uint32_t ab = sb + S_A;
#pragma unroll
        for (int it2 = 0; it2 < 2; it2++) {
            int idx = tid + it2 * 256;
            int r = idx >> 3, c = idx & 7;
            uint32_t sw = SW128((uint32_t)(r * 128 + c * 16));
            size_t go = (size_t)r * 64 + c * 8;
            cpa16(ab + sw,        g_yh + go);
            cpa16(ab + 8192 + sw, g_yl + go);
        }
    }
    CPA_COMMIT();
    __syncthreads();

    int a_row  = wm * 32 + (lane & 15);
    int a_colb = (lane >> 4) * 16;
    int b_n    = wn * 32 + ((lane >> 3) >> 1) * 8 + (lane & 7);
    int b_kb   = ((lane >> 3) & 1) * 16;

    for (int it = 0; it < 50; it++) {
        int p = it & 1;
        if (it + 1 < 50) {
            uint32_t ab = sb + S_A + (1 - p) * 16384;
#pragma unroll
            for (int it2 = 0; it2 < 2; it2++) {
                int idx = tid + it2 * 256;
                int r = idx >> 3, c = idx & 7;
                uint32_t sw = SW128((uint32_t)(r * 128 + c * 16));
                size_t go = (size_t)((it + 1) * 64 + r) * 64 + c * 8;
                cpa16(ab + sw,        g_yh + go);
                cpa16(ab + 8192 + sw, g_yl + go);
            }
        }
        CPA_COMMIT();
        CPA_WAIT1();
        __syncthreads();

        float c[2][4][4];
#pragma unroll
        for (int mb = 0; mb < 2; mb++)
#pragma unroll
            for (int nbk = 0; nbk < 4; nbk++)
#pragma unroll
                for (int j = 0; j < 4; j++) c[mb][nbk][j] = 0.f;

        uint32_t Ah = sb + S_A + p * 16384;
        uint32_t Al = Ah + 8192;
        uint32_t Bh = sb + S_BH;
        uint32_t Bl = sb + S_BL;

#pragma unroll
        for (int ks = 0; ks < 4; ks++) {
            uint32_t swa0 = SW128((uint32_t)(a_row * 128 + a_colb + ks * 32));
            uint32_t swa1 = SW128((uint32_t)((a_row + 16) * 128 + a_colb + ks * 32));
            uint32_t swb0 = SW128((uint32_t)(b_n * 128 + b_kb + ks * 32));
            uint32_t swb1 = SW128((uint32_t)((b_n + 16) * 128 + b_kb + ks * 32));

            uint32_t ah0[4], ah1[4], al0[4], al1[4];
            uint32_t bh[8], bl[8];
            ldm4(ah0[0], ah0[1], ah0[2], ah0[3], Ah + swa0);
            ldm4(ah1[0], ah1[1], ah1[2], ah1[3], Ah + swa1);
            ldm4(al0[0], al0[1], al0[2], al0[3], Al + swa0);
            ldm4(al1[0], al1[1], al1[2], al1[3], Al + swa1);
            ldm4(bh[0], bh[1], bh[2], bh[3], Bh + swb0);
            ldm4(bh[4], bh[5], bh[6], bh[7], Bh + swb1);
            ldm4(bl[0], bl[1], bl[2], bl[3], Bl + swb0);
            ldm4(bl[4], bl[5], bl[6], bl[7], Bl + swb1);

#pragma unroll
            for (int q = 0; q < 2; q++) {
                mma16816(c[0][2 * q],     ah0, bh[4 * q],     bh[4 * q + 1]);
                mma16816(c[0][2 * q + 1], ah0, bh[4 * q + 2], bh[4 * q + 3]);
                mma16816(c[1][2 * q],     ah1, bh[4 * q],     bh[4 * q + 1]);
                mma16816(c[1][2 * q + 1], ah1, bh[4 * q + 2], bh[4 * q + 3]);
                mma16816(c[0][2 * q],     ah0, bl[4 * q],     bl[4 * q + 1]);
                mma16816(c[0][2 * q + 1], ah0, bl[4 * q + 2], bl[4 * q + 3]);
                mma16816(c[1][2 * q],     ah1, bl[4 * q],     bl[4 * q + 1]);
                mma16816(c[1][2 * q + 1], ah1, bl[4 * q + 2], bl[4 * q + 3]);
                mma16816(c[0][2 * q],     al0, bh[4 * q],     bh[4 * q + 1]);
                mma16816(c[0][2 * q + 1], al0, bh[4 * q + 2], bh[4 * q + 3]);
                mma16816(c[1][2 * q],     al1, bh[4 * q],     bh[4 * q + 1]);
                mma16816(c[1][2 * q + 1], al1, bh[4 * q + 2], bh[4 * q + 3]);
            }
        }

#pragma unroll
        for (int mb = 0; mb < 2; mb++) {
            int row = it * 64 + wm * 32 + mb * 16 + g;
            float* orow = out + (size_t)row * NV;
#pragma unroll
            for (int nbk = 0; nbk < 4; nbk++) {
                int col = nb + wn * 32 + nbk * 8 + 2 * q4;
                float2 bv = bias_r[nbk];
                float2 v0 = make_float2(c[mb][nbk][0] + bv.x, c[mb][nbk][1] + bv.y);
                float2 v1 = make_float2(c[mb][nbk][2] + bv.x, c[mb][nbk][3] + bv.y);
                *(float2*)(orow + col)          = v0;
                *(float2*)(orow + 8 * NV + col) = v1;
            }
        }
        __syncthreads();
    }
}

// ---------------------------------------------------------------------------
extern "C" void kernel_launch(void* const* d_in, const int* in_sizes, int n_in,
                              void* d_out, int out_size) {
    (void)in_sizes; (void)n_in; (void)out_size;
    const int*   x  = (const int*)d_in[0];
    const float* te = (const float*)d_in[1];
    const float* pe = (const float*)d_in[2];
    const float* Wq = (const float*)d_in[3];  const float* bq = (const float*)d_in[4];
    const float* Wk = (const float*)d_in[5];  const float* bk = (const float*)d_in[6];
    const float* Wv = (const float*)d_in[7];  const float* bv = (const float*)d_in[8];
    const float* Wo = (const float*)d_in[9];  const float* bo = (const float*)d_in[10];
    const float* W1 = (const float*)d_in[11]; const float* b1 = (const float*)d_in[12];
    const float* W2 = (const float*)d_in[13]; const float* b2 = (const float*)d_in[14];
    const float* Wf = (const float*)d_in[15]; const float* bf = (const float*)d_in[16];
    float* out = (float*)d_out;

    k_cvt_wf<<<NV / 64, 256>>>(Wf);
    k_cvt_t<<<dim3(1, 16), 256>>>(Wo, OD, E, 0);    // Wo -> [64][1024]
    k_cvt_t<<<dim3(4, 1), 256>>>(W1, E, FM, 1);     // W1 -> [256][64]
    k_cvt_t<<<dim3(1, 4), 256>>>(W2, FM, E, 2);     // W2 -> [64][256]
    k_qkv<<<dim3(B, H, 3), 128>>>(x, te, pe, Wq, bq, Wk, bk, Wv, bv);

    int attn_smem = A_TOTF * (int)sizeof(float);
    cudaFuncSetAttribute(k_attn, cudaFuncAttributeMaxDynamicSharedMemorySize, attn_smem);
    k_attn<<<dim3(B, H), 256, attn_smem>>>();

    k_ffn_a<<<BT / 32, 256>>>(bo);

    cudaFuncSetAttribute(k_ffn_b, cudaFuncAttributeMaxDynamicSharedMemorySize, FB_TOT);
    k_ffn_b<<<BT / 32, 256, FB_TOT>>>(b1, b2);

    cudaFuncSetAttribute(k_logits_mma, cudaFuncAttributeMaxDynamicSharedMemorySize, S_TOT);
    k_logits_mma<<<NV / 128, 256, S_TOT>>>(bf, out);
}

// round 14
// speedup vs baseline: 1.4066x; 1.0523x over previous
#include <cuda_runtime.h>
#include <cuda_bf16.h>
#include <cuda_fp16.h>
#include <math.h>
#include <cstdint>

// ---------------------------------------------------------------------------
// SimpleGPT forward. R14: logits GEMM on fp16 2-product split
// (D = yh@Wh + (yl*1024)@Wh / 1024, W single fp16) — 33% less MMA work,
// half the W smem/traffic. FFN/attn/qkv from R13 (288.9us, validated).
// B=64 T=50 V=32000 E=64 DH=128 H=8 M=256
// ---------------------------------------------------------------------------
constexpr int B   = 64;
constexpr int T   = 50;
constexpr int NV  = 32000;
constexpr int E   = 64;
constexpr int DH  = 128;
constexpr int H   = 8;
constexpr int FM  = 256;
constexpr int BT  = B * T;
constexpr int OD  = H * DH;

typedef unsigned long long u64;

__device__ __forceinline__ u64 ffma2(u64 a, u64 b, u64 c) {
    u64 d;
    asm("fma.rn.f32x2 %0, %1, %2, %3;" : "=l"(d) : "l"(a), "l"(b), "l"(c));
    return d;
}
__device__ __forceinline__ u64 bcast2(float x) {
    u64 d;
    unsigned xi = __float_as_uint(x);
    asm("mov.b64 %0, {%1, %1};" : "=l"(d) : "r"(xi));
    return d;
}
__device__ __forceinline__ u64 pack2f(float x, float y) {
    u64 d;
    unsigned xi = __float_as_uint(x), yi = __float_as_uint(y);
    asm("mov.b64 %0, {%1, %2};" : "=l"(d) : "r"(xi), "r"(yi));
    return d;
}
__device__ __forceinline__ u64 pk(uint32_t lo, uint32_t hi) {
    u64 d;
    asm("mov.b64 %0, {%1, %2};" : "=l"(d) : "r"(lo), "r"(hi));
    return d;
}
__device__ __forceinline__ float2 unpack2(u64 v) {
    unsigned lo, hi;
    asm("mov.b64 {%0, %1}, %2;" : "=r"(lo), "=r"(hi) : "l"(v));
    return make_float2(__uint_as_float(lo), __uint_as_float(hi));
}
__device__ __forceinline__ uint32_t smem_u32(const void* p) {
    uint32_t a;
    asm("{ .reg .u64 t; cvta.to.shared.u64 t, %1; cvt.u32.u64 %0, t; }" : "=r"(a) : "l"(p));
    return a;
}
__device__ __forceinline__ void cpa16(uint32_t saddr, const void* gptr) {
    asm volatile("cp.async.cg.shared.global [%0], [%1], 16;"
                 :: "r"(saddr), "l"(__cvta_generic_to_global(gptr)) : "memory");
}
#define CPA_COMMIT() asm volatile("cp.async.commit_group;" ::: "memory")
#define CPA_WAIT1()  asm volatile("cp.async.wait_group 1;" ::: "memory")
#define SW128(x) ((x) ^ (((x) >> 3) & 0x70))

__device__ __forceinline__ float gelu_exact(float x) {
    return 0.5f * x * (1.0f + erff(x * 0.70710678118654752f));
}
__device__ __forceinline__ void split2(float v0, float v1,
                                       __nv_bfloat162& hh, __nv_bfloat162& ll) {
    __nv_bfloat16 h0 = __float2bfloat16_rn(v0);
    __nv_bfloat16 h1 = __float2bfloat16_rn(v1);
    hh.x = h0; hh.y = h1;
    ll.x = __float2bfloat16_rn(v0 - __bfloat162float(h0));
    ll.y = __float2bfloat16_rn(v1 - __bfloat162float(h1));
}

// Scratch (device globals — referenced ONLY from device code)
__device__ __align__(16) float g_q[B * H * T * DH];
__device__ __align__(16) float g_k[B * H * T * DH];
__device__ __align__(16) float g_v[B * H * T * DH];
__device__ __align__(16) __nv_bfloat16 g_oh[BT * OD];
__device__ __align__(16) __nv_bfloat16 g_ol[BT * OD];
__device__ __align__(16) __nv_bfloat16 g_ah[BT * E];
__device__ __align__(16) __nv_bfloat16 g_al[BT * E];
__device__ __align__(16) __half g_yh[BT * E];              // fp16 y hi
__device__ __align__(16) __half g_yl[BT * E];              // fp16 (y-yh)*1024
__device__ __align__(16) __half g_wh[(size_t)NV * E];      // fp16 Wf^T [n][k]
__device__ __align__(16) __nv_bfloat16 g_woTh[OD * E];
__device__ __align__(16) __nv_bfloat16 g_woTl[OD * E];
__device__ __align__(16) __nv_bfloat16 g_w1Th[FM * E];
__device__ __align__(16) __nv_bfloat16 g_w1Tl[FM * E];
__device__ __align__(16) __nv_bfloat16 g_w2Th[E * FM];
__device__ __align__(16) __nv_bfloat16 g_w2Tl[E * FM];

// ---------------------------------------------------------------------------
// 0a) Wf -> transposed fp16:  g_wh[n][k]
// ---------------------------------------------------------------------------
__global__ void k_cvt_wf(const float* __restrict__ Wf) {
    __shared__ float s[64 * 65];
    int tid = threadIdx.x;
    int nb = blockIdx.x * 64;
#pragma unroll
    for (int it = 0; it < 16; it++) {
        int i = tid + it * 256;
        int k = i >> 6, j = i & 63;
        s[k * 65 + j] = Wf[(size_t)k * NV + nb + j];
    }
    __syncthreads();
#pragma unroll
    for (int it = 0; it < 8; it++) {
        int i = tid + it * 256;
        int n = i >> 5, k2 = (i & 31) * 2;
        __half2 hh;
        hh.x = __float2half_rn(s[k2 * 65 + n]);
        hh.y = __float2half_rn(s[(k2 + 1) * 65 + n]);
        *(__half2*)(g_wh + (size_t)(nb + n) * 64 + k2) = hh;
    }
}

// ---------------------------------------------------------------------------
// 0b) Transpose+split in[R][C] fp32 -> [C][R] bf16 hi/lo (device-selected out)
// ---------------------------------------------------------------------------
__global__ void k_cvt_t(const float* __restrict__ in, int R, int C, int which) {
    __shared__ float s[64 * 65];
    int tid = threadIdx.x;
    int cb = blockIdx.x * 64, rb = blockIdx.y * 64;

    __nv_bfloat16* oh;
    __nv_bfloat16* ol;
    if (which == 0)      { oh = g_woTh; ol = g_woTl; }
    else if (which == 1) { oh = g_w1Th; ol = g_w1Tl; }
    else                 { oh = g_w2Th; ol = g_w2Tl; }

#pragma unroll
    for (int it = 0; it < 16; it++) {
        int i = tid + it * 256;
        int r = i >> 6, c = i & 63;
        s[r * 65 + c] = in[(size_t)(rb + r) * C + cb + c];
    }
    __syncthreads();
#pragma unroll
    for (int it = 0; it < 8; it++) {
        int i = tid + it * 256;
        int n = i >> 5, k2 = (i & 31) * 2;
        __nv_bfloat162 hh, ll;
        split2(s[k2 * 65 + n], s[(k2 + 1) * 65 + n], hh, ll);
        size_t o = (size_t)(cb + n) * R + rb + k2;
        *(__nv_bfloat162*)(oh + o) = hh;
        *(__nv_bfloat162*)(ol + o) = ll;
    }
}

// ---------------------------------------------------------------------------
// 1) QKV (+ fused embedding)
// ---------------------------------------------------------------------------
__global__ void k_qkv(const int* __restrict__ x,
                      const float* __restrict__ te, const float* __restrict__ pe,
                      const float* __restrict__ Wq, const float* __restrict__ bq,
                      const float* __restrict__ Wk, const float* __restrict__ bk,
                      const float* __restrict__ Wv, const float* __restrict__ bv) {
    __shared__ __align__(16) float h_s[T * E];
    int b = blockIdx.x, h = blockIdx.y, m = blockIdx.z;
    int d = threadIdx.x;

    for (int i = d; i < T * E; i += 128) {
        int t = i >> 6;
        h_s[i] = te[x[b * T + t] * E + (i & 63)] + pe[i];
    }

    const float* W    = (m == 0) ? Wq : ((m == 1) ? Wk : Wv);
    const float* bias = (m == 0) ? bq : ((m == 1) ? bk : bv);
    float* out = ((m == 0) ? g_q : ((m == 1) ? g_k : g_v)) + ((size_t)(b * H + h) * T) * DH;

    u64 wp[32];
#pragma unroll
    for (int e2 = 0; e2 < 32; e2++)
        wp[e2] = pack2f(W[(h * E + 2 * e2) * DH + d], W[(h * E + 2 * e2 + 1) * DH + d]);
    float bb = bias[h * DH + d];
    __syncthreads();

    for (int t = 0; t < T; t++) {
        u64 a0 = 0ull, a1 = 0ull;
        const u64* hp = (const u64*)(h_s + t * E);
#pragma unroll
        for (int e2 = 0; e2 < 32; e2 += 2) {
            a0 = ffma2(wp[e2],     hp[e2],     a0);
            a1 = ffma2(wp[e2 + 1], hp[e2 + 1], a1);
        }
        float2 s0 = unpack2(a0), s1 = unpack2(a1);
        out[t * DH + d] = s0.x + s0.y + s1.x + s1.y + bb;
    }
}

// ---------------------------------------------------------------------------
// 2) Attention (R6 core; epilogue emits bf16 hi/lo o)
// ---------------------------------------------------------------------------
constexpr int KP132 = 132;
constexpr int A_KOFF = T * KP132;
constexpr int A_VOFF = A_KOFF + T * DH;
constexpr int A_QOFF = A_VOFF;
constexpr int A_POFF = A_QOFF + 8 * 8 * DH;
constexpr int A_TOTF = A_POFF + 8 * 8 * 64;

__global__ void __launch_bounds__(256)
k_attn() {
    extern __shared__ float sm[];
    float* K_s = sm;
    float* V_s = sm + A_KOFF;
    float* q_s = sm + A_QOFF;
    float* p_s = sm + A_POFF;

    int b = blockIdx.x, h = blockIdx.y;
    int tid = threadIdx.x, w = tid >> 5, lane = tid & 31;
    size_t base = ((size_t)(b * H + h) * T) * DH;

    for (int i = tid; i < T * 32; i += 256) {
        int s = i >> 5, c4 = (i & 31) * 4;
        *(float4*)(K_s + s * KP132 + c4) = *(const float4*)(g_k + base + s * DH + c4);
        *(float4*)(V_s + s * DH + c4)    = *(const float4*)(g_v + base + s * DH + c4);
    }
    __syncthreads();

#pragma unroll
    for (int j = 0; j < 7; j++) {
        int t = w + 8 * j;
        if (t < T)
            *(float4*)(q_s + (w * 8 + j) * DH + lane * 4) =
                *(const float4*)(g_q + base + (size_t)t * DH + lane * 4);
    }
    __syncwarp();

    int s0 = lane, s1 = lane + 32;
    const float* k0p = K_s + s0 * KP132;
    const float* k1p = K_s + s1 * KP132;

    u64 acc[7][2];
#pragma unroll
    for (int j = 0; j < 7; j++) { acc[j][0] = 0ull; acc[j][1] = 0ull; }

#pragma unroll 8
    for (int c = 0; c < DH; c += 4) {
        uint4 k0 = *(const uint4*)(k0p + c);
        uint4 k1 = *(const uint4*)(k1p + c);
        u64 k0a = pk(k0.x, k0.y), k0b = pk(k0.z, k0.w);
        u64 k1a = pk(k1.x, k1.y), k1b = pk(k1.z, k1.w);
#pragma unroll
        for (int j = 0; j < 7; j++) {
            uint4 qv = *(const uint4*)(q_s + (w * 8 + j) * DH + c);
            u64 qa = pk(qv.x, qv.y), qb = pk(qv.z, qv.w);
            acc[j][0] = ffma2(qb, k0b, ffma2(qa, k0a, acc[j][0]));
            acc[j][1] = ffma2(qb, k1b, ffma2(qa, k1a, acc[j][1]));
        }
    }

    const float scale = 0.0883883476483184f;
    float sum[7], inv[7];
#pragma unroll
    for (int j = 0; j < 7; j++) {
        int t = w + 8 * j;
        bool valid = t < T;
        float2 f0 = unpack2(acc[j][0]);
        float2 f1 = unpack2(acc[j][1]);
        float sc0 = (f0.x + f0.y) * scale;
        float sc1 = (f1.x + f1.y) * scale;
        float e0 = (valid && s0 <= t) ? __expf(sc0) : 0.f;
        float e1 = (valid && s1 <= t) ? __expf(sc1) : 0.f;
        p_s[(w * 8 + j) * 64 + s0] = e0;
        p_s[(w * 8 + j) * 64 + s1] = e1;
        sum[j] = e0 + e1;
    }
#pragma unroll
    for (int off = 16; off; off >>= 1) {
#pragma unroll
        for (int j = 0; j < 7; j++)
            sum[j] += __shfl_xor_sync(0xffffffffu, sum[j], off);
    }
#pragma unroll
    for (int j = 0; j < 7; j++) inv[j] = 1.0f / sum[j];
    __syncwarp();

    u64 av[7][2];
#pragma unroll
    for (int j = 0; j < 7; j++) { av[j][0] = 0ull; av[j][1] = 0ull; }

    const float* vb = V_s + lane * 4;
    const float* pb = p_s + w * 8 * 64;
#pragma unroll 2
    for (int s = 0; s < T; s++) {
        uint4 vv = *(const uint4*)(vb + s * DH);
        u64 v01 = pk(vv.x, vv.y), v23 = pk(vv.z, vv.w);
#pragma unroll
        for (int j = 0; j < 7; j++) {
            u64 pj = bcast2(pb[j * 64 + s]);
            av[j][0] = ffma2(pj, v01, av[j][0]);
            av[j][1] = ffma2(pj, v23, av[j][1]);
        }
    }

#pragma unroll
    for (int j = 0; j < 7; j++) {
        int t = w + 8 * j;
        if (t < T) {
            float2 o01 = unpack2(av[j][0]), o23 = unpack2(av[j][1]);
            __nv_bfloat162 hA, lA, hB, lB;
            split2(o01.x * inv[j], o01.y * inv[j], hA, lA);
            split2(o23.x * inv[j], o23.y * inv[j], hB, lB);
            size_t o = (size_t)(b * T + t) * OD + h * DH + lane * 4;
            *(__nv_bfloat162*)(g_oh + o)     = hA;
            *(__nv_bfloat162*)(g_oh + o + 2) = hB;
            *(__nv_bfloat162*)(g_ol + o)     = lA;
            *(__nv_bfloat162*)(g_ol + o + 2) = lB;
        }
    }
}

// ---------------------------------------------------------------------------
// mma.sync helpers
// ---------------------------------------------------------------------------
__device__ __forceinline__ void ldm4(uint32_t& r0, uint32_t& r1,
                                     uint32_t& r2, uint32_t& r3, uint32_t addr) {
    asm volatile("ldmatrix.sync.aligned.m8n8.x4.shared.b16 {%0,%1,%2,%3}, [%4];"
                 : "=r"(r0), "=r"(r1), "=r"(r2), "=r"(r3) : "r"(addr));
}
__device__ __forceinline__ void mma16816(float* c, const uint32_t* a,
                                         uint32_t b0, uint32_t b1) {
    asm volatile(
        "mma.sync.aligned.m16n8k16.row.col.f32.bf16.bf16.f32 "
        "{%0,%1,%2,%3}, {%4,%5,%6,%7}, {%8,%9}, {%0,%1,%2,%3};"
        : "+f"(c[0]), "+f"(c[1]), "+f"(c[2]), "+f"(c[3])
        : "r"(a[0]), "r"(a[1]), "r"(a[2]), "r"(a[3]), "r"(b0), "r"(b1));
}
__device__ __forceinline__ void mma16816h(float* c, const uint32_t* a,
                                          uint32_t b0, uint32_t b1) {
    asm volatile(
        "mma.sync.aligned.m16n8k16.row.col.f32.f16.f16.f32 "
        "{%0,%1,%2,%3}, {%4,%5,%6,%7}, {%8,%9}, {%0,%1,%2,%3};"
        : "+f"(c[0]), "+f"(c[1]), "+f"(c[2]), "+f"(c[3])
        : "r"(a[0]), "r"(a[1]), "r"(a[2]), "r"(a[3]), "r"(b0), "r"(b1));
}

// ---------------------------------------------------------------------------
// 3a) FFN stage A: a = o @ Wo + bo -> bf16 hi/lo (R13, validated)
// ---------------------------------------------------------------------------
__global__ void __launch_bounds__(256)
k_ffn_a(const float* __restrict__ bo) {
    __shared__ __align__(16) char smem[24576];
    uint32_t sb = smem_u32(smem);
    int tid = threadIdx.x, wid = tid >> 5, lane = tid & 31;
    int rb = blockIdx.x * 32;
    int wm = wid & 1;
    int wn = wid >> 1;

    int g = lane >> 2, q4 = lane & 3;
    int a_row  = wm * 16 + (lane & 15);
    int a_colb = (lane >> 4) * 16;
    int b_n    = wn * 16 + ((lane >> 3) >> 1) * 8 + (lane & 7);
    int b_kb   = ((lane >> 3) & 1) * 16;

    float cA[2][4];
#pragma unroll
    for (int q = 0; q < 2; q++)
#pragma unroll
        for (int j = 0; j < 4; j++) cA[q][j] = 0.f;

    for (int kc = 0; kc < 16; kc++) {
        for (int i = tid; i < 512; i += 256) {
            int half = i >> 8, r = (i >> 3) & 31, c = i & 7;
            uint32_t sw = SW128((uint32_t)(r * 128 + c * 16));
            const __nv_bfloat16* src =
                (half ? g_ol : g_oh) + (size_t)(rb + r) * OD + kc * 64 + c * 8;
            *(uint4*)(smem + half * 4096 + sw) = *(const uint4*)src;
        }
        for (int i = tid; i < 1024; i += 256) {
            int half = i >> 9, n = (i >> 3) & 63, c = i & 7;
            uint32_t sw = SW128((uint32_t)(n * 128 + c * 16));
            const __nv_bfloat16* src =
                (half ? g_woTl : g_woTh) + (size_t)n * OD + kc * 64 + c * 8;
            *(uint4*)(smem + 8192 + half * 8192 + sw) = *(const uint4*)src;
        }
        __syncthreads();

        uint32_t Ah = sb, Al = sb + 4096, Bh = sb + 8192, Bl = sb + 16384;
#pragma unroll
        for (int ks = 0; ks < 4; ks++) {
            uint32_t swa = SW128((uint32_t)(a_row * 128 + a_colb + ks * 32));
            uint32_t swb = SW128((uint32_t)(b_n * 128 + b_kb + ks * 32));
            uint32_t ah[4], al[4], bh[4], bl[4];
            ldm4(ah[0], ah[1], ah[2], ah[3], Ah + swa);
            ldm4(al[0], al[1], al[2], al[3], Al + swa);
            ldm4(bh[0], bh[1], bh[2], bh[3], Bh + swb);
            ldm4(bl[0], bl[1], bl[2], bl[3], Bl + swb);
#pragma unroll
            for (int q = 0; q < 2; q++) {
                mma16816(cA[q], ah, bh[2 * q], bh[2 * q + 1]);
                mma16816(cA[q], ah, bl[2 * q], bl[2 * q + 1]);
                mma16816(cA[q], al, bh[2 * q], bh[2 * q + 1]);
            }
        }
        __syncthreads();
    }

#pragma unroll
    for (int q = 0; q < 2; q++) {
        int col = wn * 16 + q * 8 + 2 * q4;
        float b0 = bo[col], b1v = bo[col + 1];
        int r0 = rb + wm * 16 + g, r1 = r0 + 8;
        __nv_bfloat162 hh0, ll0, hh1, ll1;
        split2(cA[q][0] + b0, cA[q][1] + b1v, hh0, ll0);
        split2(cA[q][2] + b0, cA[q][3] + b1v, hh1, ll1);
        *(__nv_bfloat162*)(g_ah + r0 * 64 + col) = hh0;
        *(__nv_bfloat162*)(g_al + r0 * 64 + col) = ll0;
        *(__nv_bfloat162*)(g_ah + r1 * 64 + col) = hh1;
        *(__nv_bfloat162*)(g_al + r1 * 64 + col) = ll1;
    }
}

// ---------------------------------------------------------------------------
// 3b) FFN stage B+C (R13 structure; epilogue now emits fp16 y splits,
//     yl scaled by 1024 to stay normal)
// ---------------------------------------------------------------------------
constexpr int FB_W = 0;
constexpr int FB_A = 32768;
constexpr int FB_M = 40960;
constexpr int FB_TOT = 73728;

__global__ void __launch_bounds__(256)
k_ffn_b(const float* __restrict__ b1, const float* __restrict__ b2) {
    extern __shared__ char smem[];
    uint32_t sb = smem_u32(smem);
    int tid = threadIdx.x, wid = tid >> 5, lane = tid & 31;
    int rb = blockIdx.x * 32;
    int wm = wid & 1;
    int wn = wid >> 1;

    int g = lane >> 2, q4 = lane & 3;
    int a_row  = wm * 16 + (lane & 15);
    int a_colb = (lane >> 4) * 16;
    int bn_sub = ((lane >> 3) >> 1) * 8 + (lane & 7);
    int b_kb   = ((lane >> 3) & 1) * 16;

    for (int i = tid; i < 512; i += 256) {
        int half = i >> 8, r = (i >> 3) & 31, c = i & 7;
        uint32_t sw = SW128((uint32_t)(r * 128 + c * 16));
        const __nv_bfloat16* src =
            (half ? g_al : g_ah) + (size_t)(rb + r) * 64 + c * 8;
        *(uint4*)(smem + FB_A + half * 4096 + sw) = *(const uint4*)src;
    }

    for (int half = 0; half < 2; half++) {
        for (int i = tid; i < 2048; i += 256) {
            int hl = i >> 10;
            int idx = i & 1023;
            int nl = idx >> 3, c = idx & 7;
            uint32_t sw = SW128((uint32_t)(nl * 128 + c * 16));
            const __nv_bfloat16* src = (hl ? g_w1Tl : g_w1Th)
                + (size_t)(half * 128 + nl) * 64 + c * 8;
            *(uint4*)(smem + FB_W + hl * 16384 + sw) = *(const uint4*)src;
        }
        __syncthreads();

        float c2f[4][4];
#pragma unroll
        for (int i = 0; i < 4; i++)
#pragma unroll
            for (int j = 0; j < 4; j++) c2f[i][j] = 0.f;

        uint32_t Ah = sb + FB_A, Al = Ah + 4096;
        uint32_t Bh = sb + FB_W, Bl = Bh + 16384;
#pragma unroll
        for (int ks = 0; ks < 4; ks++) {
            uint32_t swa = SW128((uint32_t)(a_row * 128 + a_colb + ks * 32));
            uint32_t ah[4], al[4];
            ldm4(ah[0], ah[1], ah[2], ah[3], Ah + swa);
            ldm4(al[0], al[1], al[2], al[3], Al + swa);
#pragma unroll
            for (int nb2 = 0; nb2 < 2; nb2++) {
                int rowl = wn * 32 + nb2 * 16 + bn_sub;
                uint32_t swb = SW128((uint32_t)(rowl * 128 + b_kb + ks * 32));
                uint32_t bh[4], bl[4];
                ldm4(bh[0], bh[1], bh[2], bh[3], Bh + swb);
                ldm4(bl[0], bl[1], bl[2], bl[3], Bl + swb);
#pragma unroll
                for (int q = 0; q < 2; q++) {
                    mma16816(c2f[2 * nb2 + q], ah, bh[2 * q], bh[2 * q + 1]);
                    mma16816(c2f[2 * nb2 + q], ah, bl[2 * q], bl[2 * q + 1]);
                    mma16816(c2f[2 * nb2 + q], al, bh[2 * q], bh[2 * q + 1]);
                }
            }
        }

#pragma unroll
        for (int nb2 = 0; nb2 < 2; nb2++) {
#pragma unroll
            for (int q = 0; q < 2; q++) {
                int col = half * 128 + wn * 32 + nb2 * 16 + q * 8 + 2 * q4;
                float bj0 = b1[col], bj1 = b1[col + 1];
                int chunk = col >> 6, k2 = col & 63;
                const float* cf = c2f[2 * nb2 + q];
                __nv_bfloat162 hh0, ll0, hh1, ll1;
                split2(gelu_exact(cf[0] + bj0), gelu_exact(cf[1] + bj1), hh0, ll0);
                split2(gelu_exact(cf[2] + bj0), gelu_exact(cf[3] + bj1), hh1, ll1);
                uint32_t coff = (uint32_t)(FB_M + chunk * 8192);
                uint32_t sw0 = SW128((uint32_t)((wm * 16 + g) * 128 + k2 * 2));
                uint32_t sw1 = SW128((uint32_t)((wm * 16 + g + 8) * 128 + k2 * 2));
                *(__nv_bfloat162*)(smem + coff + sw0)        = hh0;
                *(__nv_bfloat162*)(smem + coff + 4096 + sw0) = ll0;
                *(__nv_bfloat162*)(smem + coff + sw1)        = hh1;
                *(__nv_bfloat162*)(smem + coff + 4096 + sw1) = ll1;
            }
        }
        __syncthreads();
    }

    float cC[2][4];
#pragma unroll
    for (int q = 0; q < 2; q++)
#pragma unroll
        for (int j = 0; j < 4; j++) cC[q][j] = 0.f;

    int b_n = wn * 16 + bn_sub;
    for (int pair = 0; pair < 2; pair++) {
        for (int i = tid; i < 2048; i += 256) {
            int cl = i >> 10;
            int rest = i & 1023;
            int hl = rest >> 9;
            int idx = rest & 511;
            int n = idx >> 3, c = idx & 7;
            uint32_t sw = SW128((uint32_t)(n * 128 + c * 16));
            const __nv_bfloat16* src = (hl ? g_w2Tl : g_w2Th)
                + (size_t)n * FM + (2 * pair + cl) * 64 + c * 8;
            *(uint4*)(smem + FB_W + cl * 16384 + hl * 8192 + sw) = *(const uint4*)src;
        }
        __syncthreads();

#pragma unroll
        for (int cl = 0; cl < 2; cl++) {
            int chunk = 2 * pair + cl;
            uint32_t Ah = sb + FB_M + chunk * 8192, Al = Ah + 4096;
            uint32_t Bh = sb + FB_W + cl * 16384,   Bl = Bh + 8192;
#pragma unroll
            for (int ks = 0; ks < 4; ks++) {
                uint32_t swa = SW128((uint32_t)(a_row * 128 + a_colb + ks * 32));
                uint32_t swb = SW128((uint32_t)(b_n * 128 + b_kb + ks * 32));
                uint32_t ah[4], al[4], bh[4], bl[4];
                ldm4(ah[0], ah[1], ah[2], ah[3], Ah + swa);
                ldm4(al[0], al[1], al[2], al[3], Al + swa);
                ldm4(bh[0], bh[1], bh[2], bh[3], Bh + swb);
                ldm4(bl[0], bl[1], bl[2], bl[3], Bl + swb);
#pragma unroll
                for (int q = 0; q < 2; q++) {
                    mma16816(cC[q], ah, bh[2 * q], bh[2 * q + 1]);
                    mma16816(cC[q], ah, bl[2 * q], bl[2 * q + 1]);
                    mma16816(cC[q], al, bh[2 * q], bh[2 * q + 1]);
                }
            }
        }
        __syncthreads();
    }

    // epilogue: +b2, fp16 split (lo scaled by 1024) -> g_yh / g_yl
#pragma unroll
    for (int q = 0; q < 2; q++) {
        int col = wn * 16 + q * 8 + 2 * q4;
        float b20 = b2[col], b21 = b2[col + 1];
        int r0 = rb + wm * 16 + g, r1 = r0 + 8;
        float y00 = cC[q][0] + b20, y01 = cC[q][1] + b21;
        float y10 = cC[q][2] + b20, y11 = cC[q][3] + b21;
        __half2 hh0, ll0, hh1, ll1;
        hh0.x = __float2half_rn(y00); hh0.y = __float2half_rn(y01);
        hh1.x = __float2half_rn(y10); hh1.y = __float2half_rn(y11);
        ll0.x = __float2half_rn((y00 - __half2float(hh0.x)) * 1024.0f);
        ll0.y = __float2half_rn((y01 - __half2float(hh0.y)) * 1024.0f);
        ll1.x = __float2half_rn((y10 - __half2float(hh1.x)) * 1024.0f);
        ll1.y = __float2half_rn((y11 - __half2float(hh1.y)) * 1024.0f);
        *(__half2*)(g_yh + r0 * 64 + col) = hh0;
        *(__half2*)(g_yl + r0 * 64 + col) = ll0;
        *(__half2*)(g_yh + r1 * 64 + col) = hh1;
        *(__half2*)(g_yl + r1 * 64 + col) = ll1;
    }
}

// ---------------------------------------------------------------------------
// 4) Logits GEMM, fp16 2-product: D = yh@Wh + (yl*1024)@Wh / 1024.
//    Persistent column-stripe, Wh resident (16KB), A dbuf (2x16KB). 48KB smem.
// ---------------------------------------------------------------------------
constexpr int S_BH = 0;          // 16384: Wh tile (128 n x 64 k fp16)
constexpr int S_A  = 16384;      // two buffers of 16KB (yh 8KB + yl 8KB)
constexpr int S_TOT = 49152;

__global__ void __launch_bounds__(256, 2)
k_logits_mma(const float* __restrict__ bf, float* __restrict__ out) {
    extern __shared__ char smem[];
    uint32_t sb = smem_u32(smem);
    int tid = threadIdx.x, wid = tid >> 5, lane = tid & 31;
    int nb = blockIdx.x * 128;
    int wm = wid & 1;
    int wn = wid >> 1;

    // stage Wh once
    for (int idx = tid; idx < 1024; idx += 256) {
        int r = idx >> 3, c = idx & 7;
        uint32_t sw = SW128((uint32_t)(r * 128 + c * 16));
        *(uint4*)(smem + S_BH + sw) =
            *(const uint4*)(g_wh + (size_t)(nb + r) * 64 + c * 8);
    }

    int g = lane >> 2, q4 = lane & 3;
    float2 bias_r[4];
#pragma unroll
    for (int nbk = 0; nbk < 4; nbk++)
        bias_r[nbk] = *(const float2*)(bf + nb + wn * 32 + nbk * 8 + 2 * q4);

    {
        uint32_t ab = sb + S_A;
#pragma unroll
        for (int it2 = 0; it2 < 2; it2++) {
            int idx = tid + it2 * 256;
            int r = idx >> 3, c = idx & 7;
            uint32_t sw = SW128((uint32_t)(r * 128 + c * 16));
            size_t go = (size_t)r * 64 + c * 8;
            cpa16(ab + sw,        g_yh + go);
            cpa16(ab + 8192 + sw, g_yl + go);
        }
    }
    CPA_COMMIT();
    __syncthreads();

    int a_row  = wm * 32 + (lane & 15);
    int a_colb = (lane >> 4) * 16;
    int b_n    = wn * 32 + ((lane >> 3) >> 1) * 8 + (lane & 7);
    int b_kb   = ((lane >> 3) & 1) * 16;

    for (int it = 0; it < 50; it++) {
        int p = it & 1;
        if (it + 1 < 50) {
            uint32_t ab = sb + S_A + (1 - p) * 16384;
#pragma unroll
            for (int it2 = 0; it2 < 2; it2++) {
                int idx = tid + it2 * 256;
                int r = idx >> 3, c = idx & 7;
                uint32_t sw = SW128((uint32_t)(r * 128 + c * 16));
                size_t go = (size_t)((it + 1) * 64 + r) * 64 + c * 8;
                cpa16(ab + sw,        g_yh + go);
                cpa16(ab + 8192 + sw, g_yl + go);
            }
        }
        CPA_COMMIT();
        CPA_WAIT1();
        __syncthreads();

        float c[2][4][4], d[2][4][4];
#pragma unroll
        for (int mb = 0; mb < 2; mb++)
#pragma unroll
            for (int nbk = 0; nbk < 4; nbk++)
#pragma unroll
                for (int j = 0; j < 4; j++) { c[mb][nbk][j] = 0.f; d[mb][nbk][j] = 0.f; }

        uint32_t Ah = sb + S_A + p * 16384;
        uint32_t Al = Ah + 8192;
        uint32_t Bh = sb + S_BH;

#pragma unroll
        for (int ks = 0; ks < 4; ks++) {
            uint32_t swa0 = SW128((uint32_t)(a_row * 128 + a_colb + ks * 32));
            uint32_t swa1 = SW128((uint32_t)((a_row + 16) * 128 + a_colb + ks * 32));
            uint32_t swb0 = SW128((uint32_t)(b_n * 128 + b_kb + ks * 32));
            uint32_t swb1 = SW128((uint32_t)((b_n + 16) * 128 + b_kb + ks * 32));

            uint32_t ah0[4], ah1[4], al0[4], al1[4];
            uint32_t bh[8];
            ldm4(ah0[0], ah0[1], ah0[2], ah0[3], Ah + swa0);
            ldm4(ah1[0], ah1[1], ah1[2], ah1[3], Ah + swa1);
            ldm4(al0[0], al0[1], al0[2], al0[3], Al + swa0);
            ldm4(al1[0], al1[1], al1[2], al1[3], Al + swa1);
            ldm4(bh[0], bh[1], bh[2], bh[3], Bh + swb0);
            ldm4(bh[4], bh[5], bh[6], bh[7], Bh + swb1);

#pragma unroll
            for (int q = 0; q < 2; q++) {
                mma16816h(c[0][2 * q],     ah0, bh[4 * q],     bh[4 * q + 1]);
                mma16816h(c[0][2 * q + 1], ah0, bh[4 * q + 2], bh[4 * q + 3]);
                mma16816h(c[1][2 * q],     ah1, bh[4 * q],     bh[4 * q + 1]);
                mma16816h(c[1][2 * q + 1], ah1, bh[4 * q + 2], bh[4 * q + 3]);
                mma16816h(d[0][2 * q],     al0, bh[4 * q],     bh[4 * q + 1]);
                mma16816h(d[0][2 * q + 1], al0, bh[4 * q + 2], bh[4 * q + 3]);
                mma16816h(d[1][2 * q],     al1, bh[4 * q],     bh[4 * q + 1]);
                mma16816h(d[1][2 * q + 1], al1, bh[4 * q + 2], bh[4 * q + 3]);
            }
        }

        const float ds = 1.0f / 1024.0f;
#pragma unroll
        for (int mb = 0; mb < 2; mb++) {
            int row = it * 64 + wm * 32 + mb * 16 + g;
            float* orow = out + (size_t)row * NV;
#pragma unroll
            for (int nbk = 0; nbk < 4; nbk++) {
                int col = nb + wn * 32 + nbk * 8 + 2 * q4;
                float2 bv = bias_r[nbk];
                float2 v0 = make_float2(c[mb][nbk][0] + d[mb][nbk][0] * ds + bv.x,
                                        c[mb][nbk][1] + d[mb][nbk][1] * ds + bv.y);
                float2 v1 = make_float2(c[mb][nbk][2] + d[mb][nbk][2] * ds + bv.x,
                                        c[mb][nbk][3] + d[mb][nbk][3] * ds + bv.y);
                *(float2*)(orow + col)          = v0;
                *(float2*)(orow + 8 * NV + col) = v1;
            }
        }
        __syncthreads();
    }
}

// ---------------------------------------------------------------------------
extern "C" void kernel_launch(void* const* d_in, const int* in_sizes, int n_in,
                              void* d_out, int out_size) {
    (void)in_sizes; (void)n_in; (void)out_size;
    const int*   x  = (const int*)d_in[0];
    const float* te = (const float*)d_in[1];
    const float* pe = (const float*)d_in[2];
    const float* Wq = (const float*)d_in[3];  const float* bq = (const float*)d_in[4];
    const float* Wk = (const float*)d_in[5];  const float* bk = (const float*)d_in[6];
    const float* Wv = (const float*)d_in[7];  const float* bv = (const float*)d_in[8];
    const float* Wo = (const float*)d_in[9];  const float* bo = (const float*)d_in[10];
    const float* W1 = (const float*)d_in[11]; const float* b1 = (const float*)d_in[12];
    const float* W2 = (const float*)d_in[13]; const float* b2 = (const float*)d_in[14];
    const float* Wf = (const float*)d_in[15]; const float* bf = (const float*)d_in[16];
    float* out = (float*)d_out;

    k_cvt_wf<<<NV / 64, 256>>>(Wf);
    k_cvt_t<<<dim3(1, 16), 256>>>(Wo, OD, E, 0);
    k_cvt_t<<<dim3(4, 1), 256>>>(W1, E, FM, 1);
    k_cvt_t<<<dim3(1, 4), 256>>>(W2, FM, E, 2);
    k_qkv<<<dim3(B, H, 3), 128>>>(x, te, pe, Wq, bq, Wk, bk, Wv, bv);

    int attn_smem = A_TOTF * (int)sizeof(float);
    cudaFuncSetAttribute(k_attn, cudaFuncAttributeMaxDynamicSharedMemorySize, attn_smem);
    k_attn<<<dim3(B, H), 256, attn_smem>>>();

    k_ffn_a<<<BT / 32, 256>>>(bo);

    cudaFuncSetAttribute(k_ffn_b, cudaFuncAttributeMaxDynamicSharedMemorySize, FB_TOT);
    k_ffn_b<<<BT / 32, 256, FB_TOT>>>(b1, b2);

    cudaFuncSetAttribute(k_logits_mma, cudaFuncAttributeMaxDynamicSharedMemorySize, S_TOT);
    k_logits_mma<<<NV / 128, 256, S_TOT>>>(bf, out);
}